// round 4
// baseline (speedup 1.0000x reference)
#include <cuda_runtime.h>
#include <math.h>

// ---------------- problem constants ----------------
namespace {
constexpr int NB   = 16;      // batch
constexpr int SEQ  = 2048;    // L
constexpr int DM   = 128;     // d_model
constexpr int DI   = 256;     // d_inner
constexpr int DS   = 16;      // d_state
constexpr int DTR  = 8;       // dt_rank
constexpr int DCONV= 4;
constexpr int NLAY = 4;
constexpr int NCLS = 5;
constexpr int BL   = NB * SEQ;          // 32768 rows
constexpr int XPD  = DTR + 2 * DS;      // 40
constexpr int NCH  = 32;                // chunks per sequence
constexpr int CH   = SEQ / NCH;         // 64 steps per chunk
constexpr float EPS = 1e-5f;
}

// ---------------- scratch (static __device__, no allocs) ----------------
__device__ float g_h    [BL * DM];            // residual stream
__device__ float g_xn   [BL * DM];            // rmsnorm output
__device__ float g_xz   [BL * 2 * DI];        // in_proj output (xm | z)
__device__ float g_xc   [BL * DI];            // conv+silu output (u)
__device__ float g_dbc  [BL * XPD];           // x_proj output (dt|B|C)
__device__ float g_delta[BL * DI];            // softplus(dt_proj)
__device__ float g_y    [BL * DI];            // scan output * silu(z)
__device__ float g_P    [NB * NCH * DI * DS]; // chunk transfer products
__device__ float g_S    [NB * NCH * DI * DS]; // chunk local end-states
__device__ float g_H0   [NB * NCH * DI * DS]; // corrected chunk init states
__device__ float g_poolp[NB * 32 * DM];       // pooled partials
__device__ float g_pooled[NB * DM];

// ---------------- encoder: h = x @ enc_w^T + enc_b ----------------
__global__ void k_encoder(const float* __restrict__ x,
                          const float* __restrict__ ew,
                          const float* __restrict__ eb) {
    int row = blockIdx.x;        // 0..BL-1
    int m   = threadIdx.x;       // 0..127
    __shared__ float xs[12];
    if (m < 12) xs[m] = x[row * 12 + m];
    __syncthreads();
    float acc = eb[m];
#pragma unroll
    for (int c = 0; c < 12; c++) acc = fmaf(xs[c], ew[m * 12 + c], acc);
    g_h[row * DM + m] = acc;
}

// ---------------- rmsnorm: g_xn = rmsnorm(g_h, w) (warp per row) ----------------
__global__ void k_rmsnorm(const float* __restrict__ w) {
    int row  = blockIdx.x * 8 + threadIdx.y;   // blockDim = (32,8)
    int lane = threadIdx.x;
    float4 v = reinterpret_cast<const float4*>(g_h)[row * (DM / 4) + lane];
    float ss = v.x * v.x + v.y * v.y + v.z * v.z + v.w * v.w;
#pragma unroll
    for (int o = 16; o; o >>= 1) ss += __shfl_xor_sync(0xffffffffu, ss, o);
    float r = rsqrtf(ss * (1.0f / DM) + EPS);
    float4 wv = reinterpret_cast<const float4*>(w)[lane];
    float4 o4 = make_float4(v.x * r * wv.x, v.y * r * wv.y,
                            v.z * r * wv.z, v.w * r * wv.w);
    reinterpret_cast<float4*>(g_xn)[row * (DM / 4) + lane] = o4;
}

// ---------------- generic tiled SGEMM: C[M,N] (+)= A[M,K] * W[N,K]^T ----------------
// MODE 0: in_proj  A=g_xn (K=128) -> C=g_xz  (N=512)
// MODE 1: x_proj   A=g_xc (K=256) -> C=g_dbc (N=40)
// MODE 2: out_proj A=g_y  (K=256) -> C=g_h   (N=128, accumulate = residual add)
template <int MODE>
__global__ void __launch_bounds__(256) k_gemm(const float* __restrict__ W) {
    constexpr int N = (MODE == 0) ? 2 * DI : (MODE == 1 ? XPD : DM);
    constexpr int K = (MODE == 0) ? DM : DI;
    constexpr bool ACC = (MODE == 2);
    constexpr bool NFULL = (N % 64 == 0);
    const float* Ag = (MODE == 0) ? g_xn : (MODE == 1 ? g_xc : g_y);
    float*       C  = (MODE == 0) ? g_xz : (MODE == 1 ? g_dbc : g_h);

    __shared__ float As[16][64];
    __shared__ float Bs[16][64];
    int tid = threadIdx.x;
    int bm  = blockIdx.x * 64;
    int bn  = blockIdx.y * 64;
    int tx  = tid & 15;
    int ty  = tid >> 4;
    int lr  = tid >> 2;          // 0..63
    int lc  = (tid & 3) * 4;     // 0,4,8,12

    float acc[4][4];
#pragma unroll
    for (int i = 0; i < 4; i++)
#pragma unroll
        for (int j = 0; j < 4; j++) acc[i][j] = 0.f;

    for (int k0 = 0; k0 < K; k0 += 16) {
        float4 av = *reinterpret_cast<const float4*>(Ag + (bm + lr) * K + k0 + lc);
        As[lc + 0][lr] = av.x; As[lc + 1][lr] = av.y;
        As[lc + 2][lr] = av.z; As[lc + 3][lr] = av.w;
        float4 bv = make_float4(0.f, 0.f, 0.f, 0.f);
        if (NFULL || (bn + lr) < N)
            bv = *reinterpret_cast<const float4*>(W + (bn + lr) * K + k0 + lc);
        Bs[lc + 0][lr] = bv.x; Bs[lc + 1][lr] = bv.y;
        Bs[lc + 2][lr] = bv.z; Bs[lc + 3][lr] = bv.w;
        __syncthreads();
#pragma unroll
        for (int k = 0; k < 16; k++) {
            float4 a  = *reinterpret_cast<const float4*>(&As[k][ty * 4]);
            float4 bq = *reinterpret_cast<const float4*>(&Bs[k][tx * 4]);
            acc[0][0] = fmaf(a.x, bq.x, acc[0][0]); acc[0][1] = fmaf(a.x, bq.y, acc[0][1]);
            acc[0][2] = fmaf(a.x, bq.z, acc[0][2]); acc[0][3] = fmaf(a.x, bq.w, acc[0][3]);
            acc[1][0] = fmaf(a.y, bq.x, acc[1][0]); acc[1][1] = fmaf(a.y, bq.y, acc[1][1]);
            acc[1][2] = fmaf(a.y, bq.z, acc[1][2]); acc[1][3] = fmaf(a.y, bq.w, acc[1][3]);
            acc[2][0] = fmaf(a.z, bq.x, acc[2][0]); acc[2][1] = fmaf(a.z, bq.y, acc[2][1]);
            acc[2][2] = fmaf(a.z, bq.z, acc[2][2]); acc[2][3] = fmaf(a.z, bq.w, acc[2][3]);
            acc[3][0] = fmaf(a.w, bq.x, acc[3][0]); acc[3][1] = fmaf(a.w, bq.y, acc[3][1]);
            acc[3][2] = fmaf(a.w, bq.z, acc[3][2]); acc[3][3] = fmaf(a.w, bq.w, acc[3][3]);
        }
        __syncthreads();
    }
#pragma unroll
    for (int i = 0; i < 4; i++) {
        int row = bm + ty * 4 + i;
#pragma unroll
        for (int j = 0; j < 4; j++) {
            int col = bn + tx * 4 + j;
            if (NFULL || col < N) {
                if (ACC) C[row * N + col] += acc[i][j];
                else     C[row * N + col]  = acc[i][j];
            }
        }
    }
}

// ---------------- causal depthwise conv (width 4) + silu ----------------
__global__ void k_conv(const float* __restrict__ cw, const float* __restrict__ cb) {
    int idx = blockIdx.x * 256 + threadIdx.x;   // (b*SEQ+l)*DI + d
    int d   = idx & (DI - 1);
    int bl  = idx >> 8;                         // DI == 256
    int l   = bl & (SEQ - 1);
    int base = (bl - l) * (2 * DI) + d;         // start of this sequence in g_xz (xm part)
    float s = cb[d];
#pragma unroll
    for (int j = 0; j < DCONV; j++) {
        int ll = l + j - (DCONV - 1);
        if (ll >= 0) s = fmaf(g_xz[base + ll * (2 * DI)], cw[d * DCONV + j], s);
    }
    float sig = __fdividef(1.0f, 1.0f + __expf(-s));
    g_xc[idx] = s * sig;
}

// ---------------- delta = softplus(dt @ dt_w^T + dt_b) ----------------
__global__ void k_dt(const float* __restrict__ dtw, const float* __restrict__ dtb) {
    int bl = blockIdx.x;
    int e  = threadIdx.x;    // 0..255
    __shared__ float dts[DTR];
    if (e < DTR) dts[e] = g_dbc[bl * XPD + e];
    __syncthreads();
    float v = dtb[e];
#pragma unroll
    for (int r = 0; r < DTR; r++) v = fmaf(dts[r], dtw[e * DTR + r], v);
    float sp = fmaxf(v, 0.0f) + log1pf(__expf(-fabsf(v)));
    g_delta[bl * DI + e] = sp;
}

// ---------------- scan pass A: per-chunk local scan -> (P, S) ----------------
// P_n = prod_t exp(delta_t A_n) = exp(A_n * sum_t delta_t)   (algebraic save)
__global__ void k_scanA(const float* __restrict__ Alog) {
    int d = threadIdx.x;                  // 0..255
    int b = blockIdx.x / NCH;
    int c = blockIdx.x % NCH;
    float A[DS];
#pragma unroll
    for (int n = 0; n < DS; n++) A[n] = -__expf(Alog[d * DS + n]);
    float S[DS];
#pragma unroll
    for (int n = 0; n < DS; n++) S[n] = 0.f;
    float dsum = 0.f;
    int l0 = b * SEQ + c * CH;            // global row of chunk start
    const float* dp = g_delta + l0 * DI + d;
    const float* up = g_xc    + l0 * DI + d;
    for (int t = 0; t < CH; t++) {
        float delta = dp[t * DI];
        float du    = delta * up[t * DI];
        dsum += delta;
        const float4* bp = reinterpret_cast<const float4*>(g_dbc + (l0 + t) * XPD + DTR);
        float4 q0 = bp[0], q1 = bp[1], q2 = bp[2], q3 = bp[3];
        float Bv[DS] = {q0.x, q0.y, q0.z, q0.w, q1.x, q1.y, q1.z, q1.w,
                        q2.x, q2.y, q2.z, q2.w, q3.x, q3.y, q3.z, q3.w};
#pragma unroll
        for (int n = 0; n < DS; n++) {
            float a = __expf(delta * A[n]);
            S[n] = fmaf(a, S[n], du * Bv[n]);
        }
    }
    int o = (blockIdx.x * DI + d) * DS;
    float4* Pp = reinterpret_cast<float4*>(g_P + o);
    float4* Sp = reinterpret_cast<float4*>(g_S + o);
#pragma unroll
    for (int q = 0; q < 4; q++) {
        Pp[q] = make_float4(__expf(A[q*4+0] * dsum), __expf(A[q*4+1] * dsum),
                            __expf(A[q*4+2] * dsum), __expf(A[q*4+3] * dsum));
        Sp[q] = make_float4(S[q*4+0], S[q*4+1], S[q*4+2], S[q*4+3]);
    }
}

// ---------------- scan pass B: chunk-boundary recurrence ----------------
__global__ void k_scanB() {
    int idx = blockIdx.x * 256 + threadIdx.x;   // (b*DI + d)*DS + n, total 65536
    int b   = idx / (DI * DS);
    int dn  = idx - b * DI * DS;
    float h = 0.f;
    for (int c = 0; c < NCH; c++) {
        int o = (b * NCH + c) * DI * DS + dn;
        g_H0[o] = h;
        h = fmaf(g_P[o], h, g_S[o]);
    }
}

// ---------------- scan pass C: corrected replay, y = (sum_n h C) + u*D, * silu(z) ----------------
__global__ void k_scanC(const float* __restrict__ Alog, const float* __restrict__ Dpl) {
    int d = threadIdx.x;
    int b = blockIdx.x / NCH;
    int c = blockIdx.x % NCH;
    float A[DS];
#pragma unroll
    for (int n = 0; n < DS; n++) A[n] = -__expf(Alog[d * DS + n]);
    float h[DS];
    {
        int o = (blockIdx.x * DI + d) * DS;
        const float4* Hp = reinterpret_cast<const float4*>(g_H0 + o);
#pragma unroll
        for (int q = 0; q < 4; q++) {
            float4 hv = Hp[q];
            h[q*4+0] = hv.x; h[q*4+1] = hv.y; h[q*4+2] = hv.z; h[q*4+3] = hv.w;
        }
    }
    float Dd = Dpl[d];
    int l0 = b * SEQ + c * CH;
    const float* dp = g_delta + l0 * DI + d;
    const float* up = g_xc    + l0 * DI + d;
    const float* zp = g_xz    + l0 * (2 * DI) + DI + d;
    float*       yp = g_y     + l0 * DI + d;
    for (int t = 0; t < CH; t++) {
        float delta = dp[t * DI];
        float u     = up[t * DI];
        float du    = delta * u;
        const float4* bp = reinterpret_cast<const float4*>(g_dbc + (l0 + t) * XPD + DTR);
        float4 q0 = bp[0], q1 = bp[1], q2 = bp[2], q3 = bp[3];   // Bm
        float4 r0 = bp[4], r1 = bp[5], r2 = bp[6], r3 = bp[7];   // Cm
        float Bv[DS] = {q0.x, q0.y, q0.z, q0.w, q1.x, q1.y, q1.z, q1.w,
                        q2.x, q2.y, q2.z, q2.w, q3.x, q3.y, q3.z, q3.w};
        float Cv[DS] = {r0.x, r0.y, r0.z, r0.w, r1.x, r1.y, r1.z, r1.w,
                        r2.x, r2.y, r2.z, r2.w, r3.x, r3.y, r3.z, r3.w};
        float y = 0.f;
#pragma unroll
        for (int n = 0; n < DS; n++) {
            float a = __expf(delta * A[n]);
            h[n] = fmaf(a, h[n], du * Bv[n]);
            y    = fmaf(h[n], Cv[n], y);
        }
        y = fmaf(u, Dd, y);
        float z  = zp[t * (2 * DI)];
        float sz = z * __fdividef(1.0f, 1.0f + __expf(-z));
        yp[t * DI] = y * sz;
    }
}

// ---------------- final rmsnorm + mean-pool partials ----------------
__global__ void k_pool(const float* __restrict__ nfw) {
    int b   = blockIdx.x;
    int seg = blockIdx.y;          // 0..31, 64 rows each
    int m   = threadIdx.x;         // 0..127
    __shared__ float red[4];
    float acc = 0.f;
    float wm  = nfw[m];
    int l0 = b * SEQ + seg * 64;
    for (int r = 0; r < 64; r++) {
        float v  = g_h[(l0 + r) * DM + m];
        float ss = v * v;
#pragma unroll
        for (int o = 16; o; o >>= 1) ss += __shfl_xor_sync(0xffffffffu, ss, o);
        if ((m & 31) == 0) red[m >> 5] = ss;
        __syncthreads();
        float tot = red[0] + red[1] + red[2] + red[3];
        acc = fmaf(v * rsqrtf(tot * (1.0f / DM) + EPS), wm, acc);
        __syncthreads();
    }
    g_poolp[(b * 32 + seg) * DM + m] = acc;
}

__global__ void k_poolred() {
    int idx = blockIdx.x * 256 + threadIdx.x;   // NB*DM = 2048
    int b = idx / DM, m = idx % DM;
    float s = 0.f;
#pragma unroll
    for (int seg = 0; seg < 32; seg++) s += g_poolp[(b * 32 + seg) * DM + m];
    g_pooled[idx] = s;
}

__global__ void k_cls(const float* __restrict__ cw, const float* __restrict__ cb,
                      float* __restrict__ out) {
    int t = threadIdx.x;
    if (t >= NB * NCLS) return;
    int b = t / NCLS, c = t % NCLS;
    float s = 0.f;
#pragma unroll 8
    for (int m = 0; m < DM; m++) s = fmaf(g_pooled[b * DM + m], cw[c * DM + m], s);
    out[t] = s * (1.0f / SEQ) + cb[c];
}

// ---------------- launch ----------------
extern "C" void kernel_launch(void* const* d_in, const int* in_sizes, int n_in,
                              void* d_out, int out_size) {
    const float* x      = (const float*)d_in[0];
    const float* enc_w  = (const float*)d_in[1];
    const float* enc_b  = (const float*)d_in[2];
    const float* norm_w = (const float*)d_in[3];
    const float* in_w   = (const float*)d_in[4];
    const float* conv_w = (const float*)d_in[5];
    const float* conv_b = (const float*)d_in[6];
    const float* xp_w   = (const float*)d_in[7];
    const float* dt_w   = (const float*)d_in[8];
    const float* dt_b   = (const float*)d_in[9];
    const float* A_log  = (const float*)d_in[10];
    const float* Dp     = (const float*)d_in[11];
    const float* out_w  = (const float*)d_in[12];
    const float* nfw    = (const float*)d_in[13];
    const float* cls_w  = (const float*)d_in[14];
    const float* cls_b  = (const float*)d_in[15];
    float* out = (float*)d_out;

    k_encoder<<<BL, DM>>>(x, enc_w, enc_b);

    for (int i = 0; i < NLAY; i++) {
        k_rmsnorm<<<BL / 8, dim3(32, 8)>>>(norm_w + i * DM);
        k_gemm<0><<<dim3(BL / 64, (2 * DI) / 64), 256>>>(in_w + i * 2 * DI * DM);
        k_conv<<<BL * DI / 256, 256>>>(conv_w + i * DI * DCONV, conv_b + i * DI);
        k_gemm<1><<<dim3(BL / 64, 1), 256>>>(xp_w + i * XPD * DI);
        k_dt<<<BL, DI>>>(dt_w + i * DI * DTR, dt_b + i * DI);
        k_scanA<<<NB * NCH, DI>>>(A_log + i * DI * DS);
        k_scanB<<<NB * DI * DS / 256, 256>>>();
        k_scanC<<<NB * NCH, DI>>>(A_log + i * DI * DS, Dp + i * DI);
        k_gemm<2><<<dim3(BL / 64, DM / 64), 256>>>(out_w + i * DM * DI);
    }

    k_pool<<<dim3(NB, 32), DM>>>(nfw);
    k_poolred<<<NB * DM / 256, 256>>>();
    k_cls<<<1, 128>>>(cls_w, cls_b, out);
}

// round 5
// speedup vs baseline: 1.0470x; 1.0470x over previous
#include <cuda_runtime.h>
#include <math.h>

// ---------------- problem constants ----------------
namespace {
constexpr int NB   = 16;      // batch
constexpr int SEQ  = 2048;    // L
constexpr int DM   = 128;     // d_model
constexpr int DI   = 256;     // d_inner
constexpr int DS   = 16;      // d_state
constexpr int DTR  = 8;       // dt_rank
constexpr int DCONV= 4;
constexpr int NLAY = 4;
constexpr int NCLS = 5;
constexpr int BL   = NB * SEQ;          // 32768 rows
constexpr int XPD  = DTR + 2 * DS;      // 40
constexpr int NCH  = 32;                // chunks per sequence
constexpr int CH   = SEQ / NCH;         // 64 steps per chunk
constexpr float EPS = 1e-5f;
}

// ---------------- scratch (static __device__, no allocs) ----------------
__device__ float g_h    [BL * DM];            // residual stream
__device__ float g_xn   [BL * DM];            // rmsnorm output
__device__ float g_xz   [BL * 2 * DI];        // in_proj output (xm | z)
__device__ float g_xc   [BL * DI];            // conv+silu output (u)
__device__ float g_dbc  [BL * XPD];           // x_proj output (dt|B|C)
__device__ float g_delta[BL * DI];            // softplus(dt_proj)
__device__ float g_y    [BL * DI];            // scan output * silu(z)
__device__ float g_P    [NB * NCH * DI * DS]; // chunk transfer products
__device__ float g_S    [NB * NCH * DI * DS]; // chunk local end-states
__device__ float g_H0   [NB * NCH * DI * DS]; // corrected chunk init states
__device__ float g_poolp[NB * 32 * DM];       // pooled partials
__device__ float g_pooled[NB * DM];

// ---------------- packed f32x2 helpers ----------------
__device__ __forceinline__ unsigned long long pk2(float lo, float hi) {
    unsigned long long r;
    asm("mov.b64 %0, {%1, %2};" : "=l"(r) : "f"(lo), "f"(hi));
    return r;
}
__device__ __forceinline__ void upk2(unsigned long long v, float& lo, float& hi) {
    asm("mov.b64 {%0, %1}, %2;" : "=f"(lo), "=f"(hi) : "l"(v));
}
__device__ __forceinline__ void ffma2(unsigned long long& d, unsigned long long a,
                                      unsigned long long b) {
    asm("fma.rn.f32x2 %0, %1, %2, %0;" : "+l"(d) : "l"(a), "l"(b));
}

// ---------------- encoder: h = x @ enc_w^T + enc_b ----------------
__global__ void k_encoder(const float* __restrict__ x,
                          const float* __restrict__ ew,
                          const float* __restrict__ eb) {
    int row = blockIdx.x;        // 0..BL-1
    int m   = threadIdx.x;       // 0..127
    __shared__ float xs[12];
    if (m < 12) xs[m] = x[row * 12 + m];
    __syncthreads();
    float acc = eb[m];
#pragma unroll
    for (int c = 0; c < 12; c++) acc = fmaf(xs[c], ew[m * 12 + c], acc);
    g_h[row * DM + m] = acc;
}

// ---------------- rmsnorm: g_xn = rmsnorm(g_h, w) (warp per row) ----------------
__global__ void k_rmsnorm(const float* __restrict__ w) {
    int row  = blockIdx.x * 8 + threadIdx.y;   // blockDim = (32,8)
    int lane = threadIdx.x;
    float4 v = reinterpret_cast<const float4*>(g_h)[row * (DM / 4) + lane];
    float ss = v.x * v.x + v.y * v.y + v.z * v.z + v.w * v.w;
#pragma unroll
    for (int o = 16; o; o >>= 1) ss += __shfl_xor_sync(0xffffffffu, ss, o);
    float r = rsqrtf(ss * (1.0f / DM) + EPS);
    float4 wv = reinterpret_cast<const float4*>(w)[lane];
    float4 o4 = make_float4(v.x * r * wv.x, v.y * r * wv.y,
                            v.z * r * wv.z, v.w * r * wv.w);
    reinterpret_cast<float4*>(g_xn)[row * (DM / 4) + lane] = o4;
}

// ---------------- packed-f32x2 SGEMM: C[M,N] (+)= A[M,K] * W[N,K]^T ----------------
// MODE 0: in_proj  A=g_xn (K=128) -> C=g_xz  (N=512) 128x128 tile, 256 thr
// MODE 1: x_proj   A=g_xc (K=256) -> C=g_dbc (N=40)  128x64  tile, 128 thr
// MODE 2: out_proj A=g_y  (K=256) -> C=g_h   (N=128, accumulate) 128x128, 256 thr
template <int MODE>
__global__ void __launch_bounds__((MODE == 1) ? 128 : 256)
k_gemm2(const float* __restrict__ W) {
    constexpr int N   = (MODE == 0) ? 2 * DI : (MODE == 1 ? XPD : DM);
    constexpr int K   = (MODE == 0) ? DM : DI;
    constexpr int TM  = 128;
    constexpr int TN  = (MODE == 1) ? 64 : 128;
    constexpr int NT  = (TM / 8) * (TN / 8);   // 256 or 128 threads
    constexpr bool ACC = (MODE == 2);
    constexpr bool NBD = (MODE == 1);          // N-bounds needed
    const float* Ag = (MODE == 0) ? g_xn : (MODE == 1 ? g_xc : g_y);
    float*       C  = (MODE == 0) ? g_xz : (MODE == 1 ? g_dbc : g_h);

    __shared__ float As[16][TM + 4];
    __shared__ float Bs[16][TN + 4];
    const int tid = threadIdx.x;
    const int bm  = blockIdx.x * TM;
    const int bn  = blockIdx.y * TN;
    const int tx  = tid % (TN / 8);            // n-group
    const int ty  = tid / (TN / 8);            // m-group (16 groups of 8 rows)

    unsigned long long acc[8][4];
#pragma unroll
    for (int i = 0; i < 8; i++)
#pragma unroll
        for (int j = 0; j < 4; j++) acc[i][j] = 0ull;

    for (int k0 = 0; k0 < K; k0 += 16) {
        // A tile: TM rows x 16 k (transposed into As[k][m])
#pragma unroll
        for (int s = tid; s < TM * 4; s += NT) {
            int row = s >> 2, kc = (s & 3) * 4;
            float4 v = *reinterpret_cast<const float4*>(Ag + (size_t)(bm + row) * K + k0 + kc);
            As[kc + 0][row] = v.x; As[kc + 1][row] = v.y;
            As[kc + 2][row] = v.z; As[kc + 3][row] = v.w;
        }
        // B tile: TN rows x 16 k
#pragma unroll
        for (int s = tid; s < TN * 4; s += NT) {
            int row = s >> 2, kc = (s & 3) * 4;
            float4 v = make_float4(0.f, 0.f, 0.f, 0.f);
            if (!NBD || (bn + row) < N)
                v = *reinterpret_cast<const float4*>(W + (size_t)(bn + row) * K + k0 + kc);
            Bs[kc + 0][row] = v.x; Bs[kc + 1][row] = v.y;
            Bs[kc + 2][row] = v.z; Bs[kc + 3][row] = v.w;
        }
        __syncthreads();
#pragma unroll
        for (int k = 0; k < 16; k++) {
            float4 a0 = *reinterpret_cast<const float4*>(&As[k][ty * 8]);
            float4 a1 = *reinterpret_cast<const float4*>(&As[k][ty * 8 + 4]);
            float4 b0 = *reinterpret_cast<const float4*>(&Bs[k][tx * 8]);
            float4 b1 = *reinterpret_cast<const float4*>(&Bs[k][tx * 8 + 4]);
            unsigned long long bp0 = pk2(b0.x, b0.y), bp1 = pk2(b0.z, b0.w);
            unsigned long long bp2 = pk2(b1.x, b1.y), bp3 = pk2(b1.z, b1.w);
            float av[8] = {a0.x, a0.y, a0.z, a0.w, a1.x, a1.y, a1.z, a1.w};
#pragma unroll
            for (int i = 0; i < 8; i++) {
                unsigned long long ad = pk2(av[i], av[i]);
                ffma2(acc[i][0], ad, bp0);
                ffma2(acc[i][1], ad, bp1);
                ffma2(acc[i][2], ad, bp2);
                ffma2(acc[i][3], ad, bp3);
            }
        }
        __syncthreads();
    }
#pragma unroll
    for (int i = 0; i < 8; i++) {
        int row = bm + ty * 8 + i;
#pragma unroll
        for (int jp = 0; jp < 4; jp++) {
            int col = bn + tx * 8 + jp * 2;
            if (!NBD || col < N) {
                float lo, hi;
                upk2(acc[i][jp], lo, hi);
                float2* p = reinterpret_cast<float2*>(C + (size_t)row * N + col);
                if (ACC) { float2 c = *p; c.x += lo; c.y += hi; *p = c; }
                else     { *p = make_float2(lo, hi); }
            }
        }
    }
}

// ---------------- causal depthwise conv (width 4) + silu : 4 rows/thread ----------------
__global__ void k_conv(const float* __restrict__ cw, const float* __restrict__ cb) {
    int d   = threadIdx.x;               // 0..255
    int bl0 = blockIdx.x * 4;            // 4 consecutive rows, same sequence
    int l   = bl0 & (SEQ - 1);
    const float* src = g_xz + (size_t)bl0 * (2 * DI) + d;
    float w0 = cw[d * 4 + 0], w1 = cw[d * 4 + 1], w2 = cw[d * 4 + 2], w3 = cw[d * 4 + 3];
    float b  = cb[d];
    float v0, v1, v2;
    if (l == 0) { v0 = v1 = v2 = 0.f; }
    else { v0 = src[-3 * 512]; v1 = src[-2 * 512]; v2 = src[-512]; }
    float v3 = src[0], v4 = src[512], v5 = src[2 * 512], v6 = src[3 * 512];
    float* dst = g_xc + (size_t)bl0 * DI + d;
    float va[7] = {v0, v1, v2, v3, v4, v5, v6};
#pragma unroll
    for (int j = 0; j < 4; j++) {
        float s = b;
        s = fmaf(va[j + 0], w0, s);
        s = fmaf(va[j + 1], w1, s);
        s = fmaf(va[j + 2], w2, s);
        s = fmaf(va[j + 3], w3, s);
        float sig = __fdividef(1.0f, 1.0f + __expf(-s));
        dst[j * DI] = s * sig;
    }
}

// ---------------- delta = softplus(dt @ dt_w^T + dt_b) ----------------
__global__ void k_dt(const float* __restrict__ dtw, const float* __restrict__ dtb) {
    int bl = blockIdx.x;
    int e  = threadIdx.x;    // 0..255
    __shared__ float dts[DTR];
    if (e < DTR) dts[e] = g_dbc[bl * XPD + e];
    __syncthreads();
    float v = dtb[e];
#pragma unroll
    for (int r = 0; r < DTR; r++) v = fmaf(dts[r], dtw[e * DTR + r], v);
    float sp = fmaxf(v, 0.0f) + log1pf(__expf(-fabsf(v)));
    g_delta[bl * DI + e] = sp;
}

// A-structure check: A_n == (n+1)*A_0 (reference data: A_log = log(1..16))
__device__ __forceinline__ bool a_is_chain(const float* A) {
    bool f = true;
#pragma unroll
    for (int n = 0; n < DS; n++)
        f = f && (fabsf(A[n] - A[0] * (float)(n + 1)) <= 1e-3f * (float)(n + 1));
    return f;
}

// ---------------- scan pass A: per-chunk local scan -> (P, S) ----------------
__global__ void k_scanA(const float* __restrict__ Alog) {
    int d = threadIdx.x;                  // 0..255
    int b = blockIdx.x / NCH;
    int c = blockIdx.x % NCH;
    float A[DS];
#pragma unroll
    for (int n = 0; n < DS; n++) A[n] = -__expf(Alog[d * DS + n]);
    bool fast = a_is_chain(A);
    float A0 = A[0];
    float S[DS];
#pragma unroll
    for (int n = 0; n < DS; n++) S[n] = 0.f;
    float dsum = 0.f;
    int l0 = b * SEQ + c * CH;
    const float* dp = g_delta + (size_t)l0 * DI + d;
    const float* up = g_xc    + (size_t)l0 * DI + d;
    if (fast) {
        for (int t = 0; t < CH; t++) {
            float delta = dp[t * DI];
            float du    = delta * up[t * DI];
            dsum += delta;
            const float4* bp = reinterpret_cast<const float4*>(g_dbc + (size_t)(l0 + t) * XPD + DTR);
            float4 q0 = bp[0], q1 = bp[1], q2 = bp[2], q3 = bp[3];
            float Bv[DS] = {q0.x, q0.y, q0.z, q0.w, q1.x, q1.y, q1.z, q1.w,
                            q2.x, q2.y, q2.z, q2.w, q3.x, q3.y, q3.z, q3.w};
            float w = __expf(delta * A0);
            float a = 1.f;
#pragma unroll
            for (int n = 0; n < DS; n++) {
                a *= w;                    // a = w^(n+1) = exp(delta*A_n)
                S[n] = fmaf(a, S[n], du * Bv[n]);
            }
        }
    } else {
        for (int t = 0; t < CH; t++) {
            float delta = dp[t * DI];
            float du    = delta * up[t * DI];
            dsum += delta;
            const float4* bp = reinterpret_cast<const float4*>(g_dbc + (size_t)(l0 + t) * XPD + DTR);
            float4 q0 = bp[0], q1 = bp[1], q2 = bp[2], q3 = bp[3];
            float Bv[DS] = {q0.x, q0.y, q0.z, q0.w, q1.x, q1.y, q1.z, q1.w,
                            q2.x, q2.y, q2.z, q2.w, q3.x, q3.y, q3.z, q3.w};
#pragma unroll
            for (int n = 0; n < DS; n++) {
                float a = __expf(delta * A[n]);
                S[n] = fmaf(a, S[n], du * Bv[n]);
            }
        }
    }
    float Pv[DS];
    if (fast) {
        float pw = __expf(dsum * A0);
        float a = 1.f;
#pragma unroll
        for (int n = 0; n < DS; n++) { a *= pw; Pv[n] = a; }
    } else {
#pragma unroll
        for (int n = 0; n < DS; n++) Pv[n] = __expf(A[n] * dsum);
    }
    int o = (blockIdx.x * DI + d) * DS;
    float4* Pp = reinterpret_cast<float4*>(g_P + o);
    float4* Sp = reinterpret_cast<float4*>(g_S + o);
#pragma unroll
    for (int q = 0; q < 4; q++) {
        Pp[q] = make_float4(Pv[q*4+0], Pv[q*4+1], Pv[q*4+2], Pv[q*4+3]);
        Sp[q] = make_float4(S[q*4+0], S[q*4+1], S[q*4+2], S[q*4+3]);
    }
}

// ---------------- scan pass B: chunk-boundary recurrence ----------------
__global__ void k_scanB() {
    int idx = blockIdx.x * 256 + threadIdx.x;   // (b*DI + d)*DS + n, total 65536
    int b   = idx / (DI * DS);
    int dn  = idx - b * DI * DS;
    float h = 0.f;
    for (int c = 0; c < NCH; c++) {
        int o = (b * NCH + c) * DI * DS + dn;
        g_H0[o] = h;
        h = fmaf(g_P[o], h, g_S[o]);
    }
}

// ---------------- scan pass C: corrected replay, y=(h.C)+u*D, *silu(z) ----------------
__global__ void k_scanC(const float* __restrict__ Alog, const float* __restrict__ Dpl) {
    int d = threadIdx.x;
    int b = blockIdx.x / NCH;
    int c = blockIdx.x % NCH;
    float A[DS];
#pragma unroll
    for (int n = 0; n < DS; n++) A[n] = -__expf(Alog[d * DS + n]);
    bool fast = a_is_chain(A);
    float A0 = A[0];
    float h[DS];
    {
        int o = (blockIdx.x * DI + d) * DS;
        const float4* Hp = reinterpret_cast<const float4*>(g_H0 + o);
#pragma unroll
        for (int q = 0; q < 4; q++) {
            float4 hv = Hp[q];
            h[q*4+0] = hv.x; h[q*4+1] = hv.y; h[q*4+2] = hv.z; h[q*4+3] = hv.w;
        }
    }
    float Dd = Dpl[d];
    int l0 = b * SEQ + c * CH;
    const float* dp = g_delta + (size_t)l0 * DI + d;
    const float* up = g_xc    + (size_t)l0 * DI + d;
    const float* zp = g_xz    + (size_t)l0 * (2 * DI) + DI + d;
    float*       yp = g_y     + (size_t)l0 * DI + d;
    for (int t = 0; t < CH; t++) {
        float delta = dp[t * DI];
        float u     = up[t * DI];
        float du    = delta * u;
        const float4* bp = reinterpret_cast<const float4*>(g_dbc + (size_t)(l0 + t) * XPD + DTR);
        float4 q0 = bp[0], q1 = bp[1], q2 = bp[2], q3 = bp[3];   // Bm
        float4 r0 = bp[4], r1 = bp[5], r2 = bp[6], r3 = bp[7];   // Cm
        float Bv[DS] = {q0.x, q0.y, q0.z, q0.w, q1.x, q1.y, q1.z, q1.w,
                        q2.x, q2.y, q2.z, q2.w, q3.x, q3.y, q3.z, q3.w};
        float Cv[DS] = {r0.x, r0.y, r0.z, r0.w, r1.x, r1.y, r1.z, r1.w,
                        r2.x, r2.y, r2.z, r2.w, r3.x, r3.y, r3.z, r3.w};
        float y = 0.f;
        if (fast) {
            float w = __expf(delta * A0);
            float a = 1.f;
#pragma unroll
            for (int n = 0; n < DS; n++) {
                a *= w;
                h[n] = fmaf(a, h[n], du * Bv[n]);
                y    = fmaf(h[n], Cv[n], y);
            }
        } else {
#pragma unroll
            for (int n = 0; n < DS; n++) {
                float a = __expf(delta * A[n]);
                h[n] = fmaf(a, h[n], du * Bv[n]);
                y    = fmaf(h[n], Cv[n], y);
            }
        }
        y = fmaf(u, Dd, y);
        float z  = zp[t * (2 * DI)];
        float sz = z * __fdividef(1.0f, 1.0f + __expf(-z));
        yp[t * DI] = y * sz;
    }
}

// ---------------- final rmsnorm + mean-pool partials ----------------
__global__ void k_pool(const float* __restrict__ nfw) {
    int b   = blockIdx.x;
    int seg = blockIdx.y;          // 0..31, 64 rows each
    int m   = threadIdx.x;         // 0..127
    __shared__ float red[4];
    float acc = 0.f;
    float wm  = nfw[m];
    int l0 = b * SEQ + seg * 64;
    for (int r = 0; r < 64; r++) {
        float v  = g_h[(size_t)(l0 + r) * DM + m];
        float ss = v * v;
#pragma unroll
        for (int o = 16; o; o >>= 1) ss += __shfl_xor_sync(0xffffffffu, ss, o);
        if ((m & 31) == 0) red[m >> 5] = ss;
        __syncthreads();
        float tot = red[0] + red[1] + red[2] + red[3];
        acc = fmaf(v * rsqrtf(tot * (1.0f / DM) + EPS), wm, acc);
        __syncthreads();
    }
    g_poolp[(b * 32 + seg) * DM + m] = acc;
}

__global__ void k_poolred() {
    int idx = blockIdx.x * 256 + threadIdx.x;   // NB*DM = 2048
    int b = idx / DM, m = idx % DM;
    float s = 0.f;
#pragma unroll
    for (int seg = 0; seg < 32; seg++) s += g_poolp[(b * 32 + seg) * DM + m];
    g_pooled[idx] = s;
}

__global__ void k_cls(const float* __restrict__ cw, const float* __restrict__ cb,
                      float* __restrict__ out) {
    int t = threadIdx.x;
    if (t >= NB * NCLS) return;
    int b = t / NCLS, c = t % NCLS;
    float s = 0.f;
#pragma unroll 8
    for (int m = 0; m < DM; m++) s = fmaf(g_pooled[b * DM + m], cw[c * DM + m], s);
    out[t] = s * (1.0f / SEQ) + cb[c];
}

// ---------------- launch ----------------
extern "C" void kernel_launch(void* const* d_in, const int* in_sizes, int n_in,
                              void* d_out, int out_size) {
    const float* x      = (const float*)d_in[0];
    const float* enc_w  = (const float*)d_in[1];
    const float* enc_b  = (const float*)d_in[2];
    const float* norm_w = (const float*)d_in[3];
    const float* in_w   = (const float*)d_in[4];
    const float* conv_w = (const float*)d_in[5];
    const float* conv_b = (const float*)d_in[6];
    const float* xp_w   = (const float*)d_in[7];
    const float* dt_w   = (const float*)d_in[8];
    const float* dt_b   = (const float*)d_in[9];
    const float* A_log  = (const float*)d_in[10];
    const float* Dp     = (const float*)d_in[11];
    const float* out_w  = (const float*)d_in[12];
    const float* nfw    = (const float*)d_in[13];
    const float* cls_w  = (const float*)d_in[14];
    const float* cls_b  = (const float*)d_in[15];
    float* out = (float*)d_out;

    k_encoder<<<BL, DM>>>(x, enc_w, enc_b);

    for (int i = 0; i < NLAY; i++) {
        k_rmsnorm<<<BL / 8, dim3(32, 8)>>>(norm_w + i * DM);
        k_gemm2<0><<<dim3(BL / 128, (2 * DI) / 128), 256>>>(in_w + i * 2 * DI * DM);
        k_conv<<<BL / 4, 256>>>(conv_w + i * DI * DCONV, conv_b + i * DI);
        k_gemm2<1><<<dim3(BL / 128, 1), 128>>>(xp_w + i * XPD * DI);
        k_dt<<<BL, DI>>>(dt_w + i * DI * DTR, dt_b + i * DI);
        k_scanA<<<NB * NCH, DI>>>(A_log + i * DI * DS);
        k_scanB<<<NB * DI * DS / 256, 256>>>();
        k_scanC<<<NB * NCH, DI>>>(A_log + i * DI * DS, Dp + i * DI);
        k_gemm2<2><<<dim3(BL / 128, 1), 256>>>(out_w + i * DM * DI);
    }

    k_pool<<<dim3(NB, 32), DM>>>(nfw);
    k_poolred<<<NB * DM / 256, 256>>>();
    k_cls<<<1, 128>>>(cls_w, cls_b, out);
}

// round 6
// speedup vs baseline: 1.0773x; 1.0290x over previous
#include <cuda_runtime.h>
#include <math.h>

// ---------------- problem constants ----------------
namespace {
constexpr int NB   = 16;      // batch
constexpr int SEQ  = 2048;    // L
constexpr int DM   = 128;     // d_model
constexpr int DI   = 256;     // d_inner
constexpr int DS   = 16;      // d_state
constexpr int DTR  = 8;       // dt_rank
constexpr int DCONV= 4;
constexpr int NLAY = 4;
constexpr int NCLS = 5;
constexpr int BL   = NB * SEQ;          // 32768 rows
constexpr int XPD  = DTR + 2 * DS;      // 40
constexpr int NCH  = 32;                // chunks per sequence
constexpr int CH   = SEQ / NCH;         // 64 steps per chunk
constexpr float EPS = 1e-5f;
}

// ---------------- scratch (static __device__, no allocs) ----------------
__device__ float g_h    [BL * DM];            // residual stream
__device__ float g_xn   [BL * DM];            // rmsnorm output
__device__ float g_xz   [BL * 2 * DI];        // in_proj output (xm | z)
__device__ float g_xc   [BL * DI];            // conv+silu output (u)
__device__ float g_dbc  [BL * XPD];           // x_proj output (dt|B|C)
__device__ float g_delta[BL * DI];            // softplus(dt_proj)
__device__ float g_y    [BL * DI];            // scan output * silu(z)
__device__ float g_P    [NB * NCH * DI * DS]; // chunk transfer products
__device__ float g_S    [NB * NCH * DI * DS]; // chunk local end-states
__device__ float g_H0   [NB * NCH * DI * DS]; // corrected chunk init states
__device__ float g_poolp[NB * 32 * DM];       // pooled partials
__device__ float g_pooled[NB * DM];

// ---------------- packed f32x2 helpers ----------------
__device__ __forceinline__ void upk2(unsigned long long v, float& lo, float& hi) {
    asm("mov.b64 {%0, %1}, %2;" : "=f"(lo), "=f"(hi) : "l"(v));
}
__device__ __forceinline__ void ffma2(unsigned long long& d, unsigned long long a,
                                      unsigned long long b) {
    asm("fma.rn.f32x2 %0, %1, %2, %0;" : "+l"(d) : "l"(a), "l"(b));
}

// ---------------- encoder: h = x @ enc_w^T + enc_b ----------------
__global__ void k_encoder(const float* __restrict__ x,
                          const float* __restrict__ ew,
                          const float* __restrict__ eb) {
    int row = blockIdx.x;        // 0..BL-1
    int m   = threadIdx.x;       // 0..127
    __shared__ float xs[12];
    if (m < 12) xs[m] = x[row * 12 + m];
    __syncthreads();
    float acc = eb[m];
#pragma unroll
    for (int c = 0; c < 12; c++) acc = fmaf(xs[c], ew[m * 12 + c], acc);
    g_h[row * DM + m] = acc;
}

// ---------------- rmsnorm: g_xn = rmsnorm(g_h, w) (warp per row) ----------------
__global__ void k_rmsnorm(const float* __restrict__ w) {
    int row  = blockIdx.x * 8 + threadIdx.y;   // blockDim = (32,8)
    int lane = threadIdx.x;
    float4 v = reinterpret_cast<const float4*>(g_h)[row * (DM / 4) + lane];
    float ss = v.x * v.x + v.y * v.y + v.z * v.z + v.w * v.w;
#pragma unroll
    for (int o = 16; o; o >>= 1) ss += __shfl_xor_sync(0xffffffffu, ss, o);
    float r = rsqrtf(ss * (1.0f / DM) + EPS);
    float4 wv = reinterpret_cast<const float4*>(w)[lane];
    float4 o4 = make_float4(v.x * r * wv.x, v.y * r * wv.y,
                            v.z * r * wv.z, v.w * r * wv.w);
    reinterpret_cast<float4*>(g_xn)[row * (DM / 4) + lane] = o4;
}

// ---------------- zero-MOV packed-f32x2 SGEMM: C[M,N] (+)= A[M,K] * W[N,K]^T ----
// A tile stored DUPLICATED in smem: each value appears twice (adjacent), so an
// LDS.128 yields two (a,a) 64-bit pairs directly usable by FFMA2 - no packing MOVs.
// B pairs are natural adjacent columns in Bs, read via LDS.128 reinterpret.
// MODE 0: in_proj  A=g_xn (K=128) -> C=g_xz  (N=512) 128x128 tile, 256 thr
// MODE 1: x_proj   A=g_xc (K=256) -> C=g_dbc (N=40)  128x64  tile, 128 thr
// MODE 2: out_proj A=g_y  (K=256) -> C=g_h   (N=128, accumulate) 128x128, 256 thr
template <int MODE>
__global__ void __launch_bounds__((MODE == 1) ? 128 : 256, (MODE == 1) ? 4 : 2)
k_gemm3(const float* __restrict__ W) {
    constexpr int N   = (MODE == 0) ? 2 * DI : (MODE == 1 ? XPD : DM);
    constexpr int K   = (MODE == 0) ? DM : DI;
    constexpr int TM  = 128;
    constexpr int TN  = (MODE == 1) ? 64 : 128;
    constexpr int NT  = (TM / 8) * (TN / 8);   // 256 or 128 threads
    constexpr bool ACC = (MODE == 2);
    constexpr bool NBD = (MODE == 1);          // N-bounds needed
    constexpr int ASTR = 2 * TM + 4;           // 260 floats: 16B-aligned rows
    constexpr int BSTR = TN + 4;               // 132 floats: 16B-aligned rows
    const float* Ag = (MODE == 0) ? g_xn : (MODE == 1 ? g_xc : g_y);
    float*       C  = (MODE == 0) ? g_xz : (MODE == 1 ? g_dbc : g_h);

    __shared__ float Asd[16 * ASTR];   // duplicated A: [k][2*m+{0,1}]
    __shared__ float Bs [16 * BSTR];   // [k][n]
    const int tid = threadIdx.x;
    const int bm  = blockIdx.x * TM;
    const int bn  = blockIdx.y * TN;
    const int tx  = tid % (TN / 8);            // n-group
    const int ty  = tid / (TN / 8);            // m-group (16 groups of 8 rows)

    unsigned long long acc[8][4];
#pragma unroll
    for (int i = 0; i < 8; i++)
#pragma unroll
        for (int j = 0; j < 4; j++) acc[i][j] = 0ull;

    for (int k0 = 0; k0 < K; k0 += 16) {
        // A tile: TM rows x 16 k, duplicated into Asd[k][2m],[2m+1]
#pragma unroll
        for (int s = tid; s < TM * 4; s += NT) {
            int row = s >> 2, kc = (s & 3) * 4;
            float4 v = *reinterpret_cast<const float4*>(Ag + (size_t)(bm + row) * K + k0 + kc);
            float2* p0 = reinterpret_cast<float2*>(&Asd[(kc + 0) * ASTR + 2 * row]);
            float2* p1 = reinterpret_cast<float2*>(&Asd[(kc + 1) * ASTR + 2 * row]);
            float2* p2 = reinterpret_cast<float2*>(&Asd[(kc + 2) * ASTR + 2 * row]);
            float2* p3 = reinterpret_cast<float2*>(&Asd[(kc + 3) * ASTR + 2 * row]);
            *p0 = make_float2(v.x, v.x);
            *p1 = make_float2(v.y, v.y);
            *p2 = make_float2(v.z, v.z);
            *p3 = make_float2(v.w, v.w);
        }
        // B tile: TN rows x 16 k
#pragma unroll
        for (int s = tid; s < TN * 4; s += NT) {
            int row = s >> 2, kc = (s & 3) * 4;
            float4 v = make_float4(0.f, 0.f, 0.f, 0.f);
            if (!NBD || (bn + row) < N)
                v = *reinterpret_cast<const float4*>(W + (size_t)(bn + row) * K + k0 + kc);
            Bs[(kc + 0) * BSTR + row] = v.x;
            Bs[(kc + 1) * BSTR + row] = v.y;
            Bs[(kc + 2) * BSTR + row] = v.z;
            Bs[(kc + 3) * BSTR + row] = v.w;
        }
        __syncthreads();
#pragma unroll
        for (int k = 0; k < 16; k++) {
            const ulonglong2* ap =
                reinterpret_cast<const ulonglong2*>(&Asd[k * ASTR + ty * 16]);
            const ulonglong2* bp =
                reinterpret_cast<const ulonglong2*>(&Bs[k * BSTR + tx * 8]);
            ulonglong2 a01 = ap[0], a23 = ap[1], a45 = ap[2], a67 = ap[3];
            ulonglong2 b03 = bp[0], b47 = bp[1];
            unsigned long long ad[8] = {a01.x, a01.y, a23.x, a23.y,
                                        a45.x, a45.y, a67.x, a67.y};
            unsigned long long bd[4] = {b03.x, b03.y, b47.x, b47.y};
#pragma unroll
            for (int i = 0; i < 8; i++) {
                ffma2(acc[i][0], ad[i], bd[0]);
                ffma2(acc[i][1], ad[i], bd[1]);
                ffma2(acc[i][2], ad[i], bd[2]);
                ffma2(acc[i][3], ad[i], bd[3]);
            }
        }
        __syncthreads();
    }
#pragma unroll
    for (int i = 0; i < 8; i++) {
        int row = bm + ty * 8 + i;
#pragma unroll
        for (int jp = 0; jp < 4; jp++) {
            int col = bn + tx * 8 + jp * 2;
            if (!NBD || col < N) {
                float lo, hi;
                upk2(acc[i][jp], lo, hi);
                float2* p = reinterpret_cast<float2*>(C + (size_t)row * N + col);
                if (ACC) { float2 c = *p; c.x += lo; c.y += hi; *p = c; }
                else     { *p = make_float2(lo, hi); }
            }
        }
    }
}

// ---------------- causal depthwise conv (width 4) + silu : 4 rows/thread ----------------
__global__ void k_conv(const float* __restrict__ cw, const float* __restrict__ cb) {
    int d   = threadIdx.x;               // 0..255
    int bl0 = blockIdx.x * 4;            // 4 consecutive rows, same sequence
    int l   = bl0 & (SEQ - 1);
    const float* src = g_xz + (size_t)bl0 * (2 * DI) + d;
    float w0 = cw[d * 4 + 0], w1 = cw[d * 4 + 1], w2 = cw[d * 4 + 2], w3 = cw[d * 4 + 3];
    float b  = cb[d];
    float v0, v1, v2;
    if (l == 0) { v0 = v1 = v2 = 0.f; }
    else { v0 = src[-3 * 512]; v1 = src[-2 * 512]; v2 = src[-512]; }
    float v3 = src[0], v4 = src[512], v5 = src[2 * 512], v6 = src[3 * 512];
    float* dst = g_xc + (size_t)bl0 * DI + d;
    float va[7] = {v0, v1, v2, v3, v4, v5, v6};
#pragma unroll
    for (int j = 0; j < 4; j++) {
        float s = b;
        s = fmaf(va[j + 0], w0, s);
        s = fmaf(va[j + 1], w1, s);
        s = fmaf(va[j + 2], w2, s);
        s = fmaf(va[j + 3], w3, s);
        float sig = __fdividef(1.0f, 1.0f + __expf(-s));
        dst[j * DI] = s * sig;
    }
}

// ---------------- delta = softplus(dt @ dt_w^T + dt_b), 4 rows/block ----------------
__global__ void k_dt(const float* __restrict__ dtw, const float* __restrict__ dtb) {
    int bl0 = blockIdx.x * 4;
    int e   = threadIdx.x;    // 0..255
    __shared__ float dts[4][DTR];
    if (e < 4 * DTR) dts[e >> 3][e & 7] = g_dbc[(size_t)(bl0 + (e >> 3)) * XPD + (e & 7)];
    __syncthreads();
    float w[DTR];
#pragma unroll
    for (int r = 0; r < DTR; r++) w[r] = dtw[e * DTR + r];
    float bb = dtb[e];
#pragma unroll
    for (int q = 0; q < 4; q++) {
        float v = bb;
#pragma unroll
        for (int r = 0; r < DTR; r++) v = fmaf(dts[q][r], w[r], v);
        float ex = __expf(-fabsf(v));
        float sp = fmaxf(v, 0.0f) + __logf(1.0f + ex);
        g_delta[(size_t)(bl0 + q) * DI + e] = sp;
    }
}

// A-structure check: A_n == (n+1)*A_0 (reference data: A_log = log(1..16))
__device__ __forceinline__ bool a_is_chain(const float* A) {
    bool f = true;
#pragma unroll
    for (int n = 0; n < DS; n++)
        f = f && (fabsf(A[n] - A[0] * (float)(n + 1)) <= 1e-3f * (float)(n + 1));
    return f;
}

// ---------------- scan pass A: per-chunk local scan -> (P, S) ----------------
__global__ void k_scanA(const float* __restrict__ Alog) {
    int d = threadIdx.x;                  // 0..255
    int b = blockIdx.x / NCH;
    int c = blockIdx.x % NCH;
    float A[DS];
#pragma unroll
    for (int n = 0; n < DS; n++) A[n] = -__expf(Alog[d * DS + n]);
    bool fast = a_is_chain(A);
    float A0 = A[0];
    float S[DS];
#pragma unroll
    for (int n = 0; n < DS; n++) S[n] = 0.f;
    float dsum = 0.f;
    int l0 = b * SEQ + c * CH;
    const float* dp = g_delta + (size_t)l0 * DI + d;
    const float* up = g_xc    + (size_t)l0 * DI + d;
    if (fast) {
        for (int t = 0; t < CH; t++) {
            float delta = dp[t * DI];
            float du    = delta * up[t * DI];
            dsum += delta;
            const float4* bp = reinterpret_cast<const float4*>(g_dbc + (size_t)(l0 + t) * XPD + DTR);
            float4 q0 = bp[0], q1 = bp[1], q2 = bp[2], q3 = bp[3];
            float Bv[DS] = {q0.x, q0.y, q0.z, q0.w, q1.x, q1.y, q1.z, q1.w,
                            q2.x, q2.y, q2.z, q2.w, q3.x, q3.y, q3.z, q3.w};
            float w = __expf(delta * A0);
            float a = 1.f;
#pragma unroll
            for (int n = 0; n < DS; n++) {
                a *= w;                    // a = w^(n+1) = exp(delta*A_n)
                S[n] = fmaf(a, S[n], du * Bv[n]);
            }
        }
    } else {
        for (int t = 0; t < CH; t++) {
            float delta = dp[t * DI];
            float du    = delta * up[t * DI];
            dsum += delta;
            const float4* bp = reinterpret_cast<const float4*>(g_dbc + (size_t)(l0 + t) * XPD + DTR);
            float4 q0 = bp[0], q1 = bp[1], q2 = bp[2], q3 = bp[3];
            float Bv[DS] = {q0.x, q0.y, q0.z, q0.w, q1.x, q1.y, q1.z, q1.w,
                            q2.x, q2.y, q2.z, q2.w, q3.x, q3.y, q3.z, q3.w};
#pragma unroll
            for (int n = 0; n < DS; n++) {
                float a = __expf(delta * A[n]);
                S[n] = fmaf(a, S[n], du * Bv[n]);
            }
        }
    }
    float Pv[DS];
    if (fast) {
        float pw = __expf(dsum * A0);
        float a = 1.f;
#pragma unroll
        for (int n = 0; n < DS; n++) { a *= pw; Pv[n] = a; }
    } else {
#pragma unroll
        for (int n = 0; n < DS; n++) Pv[n] = __expf(A[n] * dsum);
    }
    int o = (blockIdx.x * DI + d) * DS;
    float4* Pp = reinterpret_cast<float4*>(g_P + o);
    float4* Sp = reinterpret_cast<float4*>(g_S + o);
#pragma unroll
    for (int q = 0; q < 4; q++) {
        Pp[q] = make_float4(Pv[q*4+0], Pv[q*4+1], Pv[q*4+2], Pv[q*4+3]);
        Sp[q] = make_float4(S[q*4+0], S[q*4+1], S[q*4+2], S[q*4+3]);
    }
}

// ---------------- scan pass B: chunk-boundary recurrence ----------------
__global__ void k_scanB() {
    int idx = blockIdx.x * 256 + threadIdx.x;   // (b*DI + d)*DS + n, total 65536
    int b   = idx / (DI * DS);
    int dn  = idx - b * DI * DS;
    float h = 0.f;
    for (int c = 0; c < NCH; c++) {
        int o = (b * NCH + c) * DI * DS + dn;
        g_H0[o] = h;
        h = fmaf(g_P[o], h, g_S[o]);
    }
}

// ---------------- scan pass C: corrected replay, y=(h.C)+u*D, *silu(z) ----------------
__global__ void k_scanC(const float* __restrict__ Alog, const float* __restrict__ Dpl) {
    int d = threadIdx.x;
    int b = blockIdx.x / NCH;
    int c = blockIdx.x % NCH;
    float A[DS];
#pragma unroll
    for (int n = 0; n < DS; n++) A[n] = -__expf(Alog[d * DS + n]);
    bool fast = a_is_chain(A);
    float A0 = A[0];
    float h[DS];
    {
        int o = (blockIdx.x * DI + d) * DS;
        const float4* Hp = reinterpret_cast<const float4*>(g_H0 + o);
#pragma unroll
        for (int q = 0; q < 4; q++) {
            float4 hv = Hp[q];
            h[q*4+0] = hv.x; h[q*4+1] = hv.y; h[q*4+2] = hv.z; h[q*4+3] = hv.w;
        }
    }
    float Dd = Dpl[d];
    int l0 = b * SEQ + c * CH;
    const float* dp = g_delta + (size_t)l0 * DI + d;
    const float* up = g_xc    + (size_t)l0 * DI + d;
    const float* zp = g_xz    + (size_t)l0 * (2 * DI) + DI + d;
    float*       yp = g_y     + (size_t)l0 * DI + d;
    for (int t = 0; t < CH; t++) {
        float delta = dp[t * DI];
        float u     = up[t * DI];
        float du    = delta * u;
        const float4* bp = reinterpret_cast<const float4*>(g_dbc + (size_t)(l0 + t) * XPD + DTR);
        float4 q0 = bp[0], q1 = bp[1], q2 = bp[2], q3 = bp[3];   // Bm
        float4 r0 = bp[4], r1 = bp[5], r2 = bp[6], r3 = bp[7];   // Cm
        float Bv[DS] = {q0.x, q0.y, q0.z, q0.w, q1.x, q1.y, q1.z, q1.w,
                        q2.x, q2.y, q2.z, q2.w, q3.x, q3.y, q3.z, q3.w};
        float Cv[DS] = {r0.x, r0.y, r0.z, r0.w, r1.x, r1.y, r1.z, r1.w,
                        r2.x, r2.y, r2.z, r2.w, r3.x, r3.y, r3.z, r3.w};
        float y = 0.f;
        if (fast) {
            float w = __expf(delta * A0);
            float a = 1.f;
#pragma unroll
            for (int n = 0; n < DS; n++) {
                a *= w;
                h[n] = fmaf(a, h[n], du * Bv[n]);
                y    = fmaf(h[n], Cv[n], y);
            }
        } else {
#pragma unroll
            for (int n = 0; n < DS; n++) {
                float a = __expf(delta * A[n]);
                h[n] = fmaf(a, h[n], du * Bv[n]);
                y    = fmaf(h[n], Cv[n], y);
            }
        }
        y = fmaf(u, Dd, y);
        float z  = zp[t * (2 * DI)];
        float sz = z * __fdividef(1.0f, 1.0f + __expf(-z));
        yp[t * DI] = y * sz;
    }
}

// ---------------- final rmsnorm + mean-pool partials ----------------
__global__ void k_pool(const float* __restrict__ nfw) {
    int b   = blockIdx.x;
    int seg = blockIdx.y;          // 0..31, 64 rows each
    int m   = threadIdx.x;         // 0..127
    __shared__ float red[4];
    float acc = 0.f;
    float wm  = nfw[m];
    int l0 = b * SEQ + seg * 64;
    for (int r = 0; r < 64; r++) {
        float v  = g_h[(size_t)(l0 + r) * DM + m];
        float ss = v * v;
#pragma unroll
        for (int o = 16; o; o >>= 1) ss += __shfl_xor_sync(0xffffffffu, ss, o);
        if ((m & 31) == 0) red[m >> 5] = ss;
        __syncthreads();
        float tot = red[0] + red[1] + red[2] + red[3];
        acc = fmaf(v * rsqrtf(tot * (1.0f / DM) + EPS), wm, acc);
        __syncthreads();
    }
    g_poolp[(b * 32 + seg) * DM + m] = acc;
}

__global__ void k_poolred() {
    int idx = blockIdx.x * 256 + threadIdx.x;   // NB*DM = 2048
    int b = idx / DM, m = idx % DM;
    float s = 0.f;
#pragma unroll
    for (int seg = 0; seg < 32; seg++) s += g_poolp[(b * 32 + seg) * DM + m];
    g_pooled[idx] = s;
}

__global__ void k_cls(const float* __restrict__ cw, const float* __restrict__ cb,
                      float* __restrict__ out) {
    int t = threadIdx.x;
    if (t >= NB * NCLS) return;
    int b = t / NCLS, c = t % NCLS;
    float s = 0.f;
#pragma unroll 8
    for (int m = 0; m < DM; m++) s = fmaf(g_pooled[b * DM + m], cw[c * DM + m], s);
    out[t] = s * (1.0f / SEQ) + cb[c];
}

// ---------------- launch ----------------
extern "C" void kernel_launch(void* const* d_in, const int* in_sizes, int n_in,
                              void* d_out, int out_size) {
    const float* x      = (const float*)d_in[0];
    const float* enc_w  = (const float*)d_in[1];
    const float* enc_b  = (const float*)d_in[2];
    const float* norm_w = (const float*)d_in[3];
    const float* in_w   = (const float*)d_in[4];
    const float* conv_w = (const float*)d_in[5];
    const float* conv_b = (const float*)d_in[6];
    const float* xp_w   = (const float*)d_in[7];
    const float* dt_w   = (const float*)d_in[8];
    const float* dt_b   = (const float*)d_in[9];
    const float* A_log  = (const float*)d_in[10];
    const float* Dp     = (const float*)d_in[11];
    const float* out_w  = (const float*)d_in[12];
    const float* nfw    = (const float*)d_in[13];
    const float* cls_w  = (const float*)d_in[14];
    const float* cls_b  = (const float*)d_in[15];
    float* out = (float*)d_out;

    k_encoder<<<BL, DM>>>(x, enc_w, enc_b);

    for (int i = 0; i < NLAY; i++) {
        k_rmsnorm<<<BL / 8, dim3(32, 8)>>>(norm_w + i * DM);
        k_gemm3<0><<<dim3(BL / 128, (2 * DI) / 128), 256>>>(in_w + i * 2 * DI * DM);
        k_conv<<<BL / 4, 256>>>(conv_w + i * DI * DCONV, conv_b + i * DI);
        k_gemm3<1><<<dim3(BL / 128, 1), 128>>>(xp_w + i * XPD * DI);
        k_dt<<<BL / 4, 256>>>(dt_w + i * DI * DTR, dt_b + i * DI);
        k_scanA<<<NB * NCH, DI>>>(A_log + i * DI * DS);
        k_scanB<<<NB * DI * DS / 256, 256>>>();
        k_scanC<<<NB * NCH, DI>>>(A_log + i * DI * DS, Dp + i * DI);
        k_gemm3<2><<<dim3(BL / 128, 1), 256>>>(out_w + i * DM * DI);
    }

    k_pool<<<dim3(NB, 32), DM>>>(nfw);
    k_poolred<<<NB * DM / 256, 256>>>();
    k_cls<<<1, 128>>>(cls_w, cls_b, out);
}

// round 9
// speedup vs baseline: 1.4330x; 1.3301x over previous
#include <cuda_runtime.h>
#include <cuda_bf16.h>
#include <math.h>
#include <cstdint>

// ---------------- problem constants ----------------
namespace {
constexpr int NB   = 16;      // batch
constexpr int SEQ  = 2048;    // L
constexpr int DM   = 128;     // d_model
constexpr int DI   = 256;     // d_inner
constexpr int DS   = 16;      // d_state
constexpr int DTR  = 8;       // dt_rank
constexpr int NLAY = 4;
constexpr int NCLS = 5;
constexpr int BL   = NB * SEQ;          // 32768 rows
constexpr int XPD  = DTR + 2 * DS;      // 40
constexpr int NCH  = 32;                // chunks per sequence
constexpr int CH   = SEQ / NCH;         // 64 steps per chunk
constexpr float EPS = 1e-5f;
}

// ---------------- scratch (static __device__, no allocs) ----------------
__device__ float g_h    [BL * DM];            // residual stream
__device__ float g_xz   [BL * 2 * DI];        // in_proj output (xm | z)
__device__ float g_xc   [BL * DI];            // conv+silu output (u), fp32 for scan
__device__ float g_dbc  [BL * XPD];           // x_proj output (dt|B|C)
__device__ float g_delta[BL * DI];            // softplus(dt_proj)
__device__ float g_P    [NB * NCH * DI * DS];
__device__ float g_S    [NB * NCH * DI * DS];
__device__ float g_H0   [NB * NCH * DI * DS];
__device__ float g_poolp[NB * 32 * DM];
__device__ float g_pooled[NB * DM];

// bf16 hi/lo split activations (A operands)
__device__ __nv_bfloat16 g_xnh[BL * DM],  g_xnl[BL * DM];   // rmsnorm out
__device__ __nv_bfloat16 g_xch[BL * DI],  g_xcl[BL * DI];   // conv out
__device__ __nv_bfloat16 g_yh [BL * DI],  g_yl [BL * DI];   // scan out

// bf16 hi/lo split weights (B operands), xp padded 40->64 rows with zeros
__device__ __nv_bfloat16 g_wih[NLAY * 512 * 128], g_wil[NLAY * 512 * 128];
__device__ __nv_bfloat16 g_wxh[NLAY * 64 * 256],  g_wxl[NLAY * 64 * 256];
__device__ __nv_bfloat16 g_woh[NLAY * 128 * 256], g_wol[NLAY * 128 * 256];

// ---------------- helpers ----------------
__device__ __forceinline__ uint32_t smem_u32(const void* p) {
    uint32_t a;
    asm("{ .reg .u64 t; cvta.to.shared.u64 t, %1; cvt.u32.u64 %0, t; }"
        : "=r"(a) : "l"(p));
    return a;
}
__device__ __forceinline__ void ldsm4(uint32_t a, uint32_t& r0, uint32_t& r1,
                                      uint32_t& r2, uint32_t& r3) {
    asm volatile("ldmatrix.sync.aligned.m8n8.x4.shared.b16 {%0,%1,%2,%3}, [%4];"
                 : "=r"(r0), "=r"(r1), "=r"(r2), "=r"(r3) : "r"(a));
}
__device__ __forceinline__ void hmma(float* c, uint32_t a0, uint32_t a1, uint32_t a2,
                                     uint32_t a3, uint32_t b0, uint32_t b1) {
    asm volatile(
        "mma.sync.aligned.m16n8k16.row.col.f32.bf16.bf16.f32 "
        "{%0,%1,%2,%3}, {%4,%5,%6,%7}, {%8,%9}, {%0,%1,%2,%3};"
        : "+f"(c[0]), "+f"(c[1]), "+f"(c[2]), "+f"(c[3])
        : "r"(a0), "r"(a1), "r"(a2), "r"(a3), "r"(b0), "r"(b1));
}
__device__ __forceinline__ void bf16split(float x, __nv_bfloat16& h, __nv_bfloat16& l) {
    h = __float2bfloat16(x);
    l = __float2bfloat16(x - __bfloat162float(h));
}

// ---------------- weight conversion (once per launch) ----------------
__global__ void k_cvtw(const float* __restrict__ in_w,
                       const float* __restrict__ xp_w,
                       const float* __restrict__ out_w) {
    int i = blockIdx.x * 256 + threadIdx.x;
    if (i < NLAY * 512 * 128) {
        __nv_bfloat16 h, l; bf16split(in_w[i], h, l);
        g_wih[i] = h; g_wil[i] = l;
    }
    if (i < NLAY * 64 * 256) {
        int l4 = i / (64 * 256);
        int r  = (i / 256) % 64;
        int c  = i % 256;
        float x = (r < XPD) ? xp_w[((size_t)l4 * XPD + r) * 256 + c] : 0.f;
        __nv_bfloat16 h, l; bf16split(x, h, l);
        g_wxh[i] = h; g_wxl[i] = l;
    }
    if (i < NLAY * 128 * 256) {
        __nv_bfloat16 h, l; bf16split(out_w[i], h, l);
        g_woh[i] = h; g_wol[i] = l;
    }
}

// ---------------- encoder: h = x @ enc_w^T + enc_b ----------------
__global__ void k_encoder(const float* __restrict__ x,
                          const float* __restrict__ ew,
                          const float* __restrict__ eb) {
    int row = blockIdx.x;
    int m   = threadIdx.x;
    __shared__ float xs[12];
    if (m < 12) xs[m] = x[row * 12 + m];
    __syncthreads();
    float acc = eb[m];
#pragma unroll
    for (int c = 0; c < 12; c++) acc = fmaf(xs[c], ew[m * 12 + c], acc);
    g_h[row * DM + m] = acc;
}

// ---------------- rmsnorm -> bf16 hi/lo ----------------
__global__ void k_rmsnorm(const float* __restrict__ w) {
    int row  = blockIdx.x * 8 + threadIdx.y;   // blockDim (32,8)
    int lane = threadIdx.x;
    float4 v = reinterpret_cast<const float4*>(g_h)[row * (DM / 4) + lane];
    float ss = v.x * v.x + v.y * v.y + v.z * v.z + v.w * v.w;
#pragma unroll
    for (int o = 16; o; o >>= 1) ss += __shfl_xor_sync(0xffffffffu, ss, o);
    float r = rsqrtf(ss * (1.0f / DM) + EPS);
    float4 wv = reinterpret_cast<const float4*>(w)[lane];
    float o0 = v.x * r * wv.x, o1 = v.y * r * wv.y;
    float o2 = v.z * r * wv.z, o3 = v.w * r * wv.w;
    __nv_bfloat16 h0, l0, h1, l1, h2, l2, h3, l3;
    bf16split(o0, h0, l0); bf16split(o1, h1, l1);
    bf16split(o2, h2, l2); bf16split(o3, h3, l3);
    size_t base = (size_t)row * DM + lane * 4;
    *reinterpret_cast<__nv_bfloat162*>(g_xnh + base)     = __nv_bfloat162(h0, h1);
    *reinterpret_cast<__nv_bfloat162*>(g_xnh + base + 2) = __nv_bfloat162(h2, h3);
    *reinterpret_cast<__nv_bfloat162*>(g_xnl + base)     = __nv_bfloat162(l0, l1);
    *reinterpret_cast<__nv_bfloat162*>(g_xnl + base + 2) = __nv_bfloat162(l2, l3);
}

// ---------------- HMMA 3-split GEMM: C[M,N] (+)= A[M,K] * W[N,K]^T ----------
// D = Ah*Wh + Al*Wh + Ah*Wl  (drops lo*lo, ~2^-18 term)
// Weight pointers resolved IN DEVICE CODE from the layer index (a __device__
// symbol used in host code yields the host shadow address -> ATS-read zeros).
// MODE 0: in_proj  A=g_xnh/l (K=128) -> g_xz  (N=512, grid.y=4)
// MODE 1: x_proj   A=g_xch/l (K=256) -> g_dbc (N=40 real, TN=64)
// MODE 2: out_proj A=g_yh/l  (K=256) -> g_h   (N=128, accumulate)
template <int MODE>
__global__ void __launch_bounds__(256) k_mma(int layer) {
    constexpr int K   = (MODE == 0) ? 128 : 256;
    constexpr int TN  = (MODE == 1) ? 64 : 128;
    constexpr int NF  = TN / 16;              // n-frags per warp (warp ntile TN/2)
    constexpr bool ACC = (MODE == 2);
    constexpr int STR = 40;                   // smem row stride in bf16

    __shared__ __align__(16) __nv_bfloat16 sAh[128 * STR];
    __shared__ __align__(16) __nv_bfloat16 sAl[128 * STR];
    __shared__ __align__(16) __nv_bfloat16 sBh[128 * STR];
    __shared__ __align__(16) __nv_bfloat16 sBl[128 * STR];

    const __nv_bfloat16* Ah = (MODE == 0) ? g_xnh : (MODE == 1 ? g_xch : g_yh);
    const __nv_bfloat16* Al = (MODE == 0) ? g_xnl : (MODE == 1 ? g_xcl : g_yl);
    const __nv_bfloat16* Wh;
    const __nv_bfloat16* Wl;
    if (MODE == 0) {
        Wh = g_wih + (size_t)layer * 512 * 128;
        Wl = g_wil + (size_t)layer * 512 * 128;
    } else if (MODE == 1) {
        Wh = g_wxh + (size_t)layer * 64 * 256;
        Wl = g_wxl + (size_t)layer * 64 * 256;
    } else {
        Wh = g_woh + (size_t)layer * 128 * 256;
        Wl = g_wol + (size_t)layer * 128 * 256;
    }
    float* C  = (MODE == 0) ? g_xz : (MODE == 1 ? g_dbc : g_h);
    const int ldC = (MODE == 0) ? 512 : (MODE == 1 ? XPD : DM);

    const int tid = threadIdx.x;
    const int lid = tid & 31;
    const int wid = tid >> 5;
    const int mw  = wid & 3;                  // 0..3
    const int nw  = wid >> 2;                 // 0..1
    const int bm  = blockIdx.x * 128;
    const int bn  = blockIdx.y * TN;
    const int rb0 = mw * 32;                  // warp m base in tile
    const int nb0 = nw * (TN / 2);            // warp n base in tile

    const uint32_t bAh = smem_u32(sAh), bAl = smem_u32(sAl);
    const uint32_t bBh = smem_u32(sBh), bBl = smem_u32(sBl);

    // lane offsets for ldmatrix (bf16 element units)
    const int arow = (lid & 7) + ((lid >> 3) & 1) * 8;
    const int acol = (lid >> 4) * 8;
    const int brow = (lid & 7) + ((lid >> 3) >= 2 ? 8 : 0);
    const int bcol = ((lid >> 3) & 1) * 8;

    float acc[2][NF][4];
#pragma unroll
    for (int mi = 0; mi < 2; mi++)
#pragma unroll
        for (int ni = 0; ni < NF; ni++)
#pragma unroll
            for (int q = 0; q < 4; q++) acc[mi][ni][q] = 0.f;

    for (int k0 = 0; k0 < K; k0 += 32) {
        // stage A tiles (128 x 32)
        for (int s = tid; s < 512; s += 256) {
            int row = s >> 2, c8 = (s & 3) * 8;
            size_t go = (size_t)(bm + row) * K + k0 + c8;
            *reinterpret_cast<uint4*>(sAh + row * STR + c8) =
                *reinterpret_cast<const uint4*>(Ah + go);
            *reinterpret_cast<uint4*>(sAl + row * STR + c8) =
                *reinterpret_cast<const uint4*>(Al + go);
        }
        // stage B tiles (TN x 32)
        for (int s = tid; s < TN * 4; s += 256) {
            int row = s >> 2, c8 = (s & 3) * 8;
            size_t go = (size_t)(bn + row) * K + k0 + c8;
            *reinterpret_cast<uint4*>(sBh + row * STR + c8) =
                *reinterpret_cast<const uint4*>(Wh + go);
            *reinterpret_cast<uint4*>(sBl + row * STR + c8) =
                *reinterpret_cast<const uint4*>(Wl + go);
        }
        __syncthreads();

#pragma unroll
        for (int pass = 0; pass < 3; pass++) {
            uint32_t aB = (pass == 1) ? bAl : bAh;
            uint32_t bB = (pass == 2) ? bBl : bBh;
#pragma unroll
            for (int ks = 0; ks < 32; ks += 16) {
                uint32_t af[2][4];
#pragma unroll
                for (int mi = 0; mi < 2; mi++) {
                    uint32_t addr = aB +
                        (uint32_t)(((rb0 + mi * 16 + arow) * STR + ks + acol) * 2);
                    ldsm4(addr, af[mi][0], af[mi][1], af[mi][2], af[mi][3]);
                }
                uint32_t bf[NF][2];
#pragma unroll
                for (int nj = 0; nj < NF / 2; nj++) {
                    uint32_t r0, r1, r2, r3;
                    uint32_t addr = bB +
                        (uint32_t)(((nb0 + nj * 16 + brow) * STR + ks + bcol) * 2);
                    ldsm4(addr, r0, r1, r2, r3);
                    bf[nj * 2][0] = r0; bf[nj * 2][1] = r1;
                    bf[nj * 2 + 1][0] = r2; bf[nj * 2 + 1][1] = r3;
                }
#pragma unroll
                for (int mi = 0; mi < 2; mi++)
#pragma unroll
                    for (int ni = 0; ni < NF; ni++)
                        hmma(acc[mi][ni], af[mi][0], af[mi][1], af[mi][2], af[mi][3],
                             bf[ni][0], bf[ni][1]);
            }
        }
        __syncthreads();
    }

    // epilogue
    const int g = lid >> 2, t = lid & 3;
#pragma unroll
    for (int mi = 0; mi < 2; mi++) {
        int row0 = bm + rb0 + mi * 16 + g;
#pragma unroll
        for (int ni = 0; ni < NF; ni++) {
            int col = bn + nb0 + ni * 8 + t * 2;
            if (MODE == 1 && col >= XPD) continue;
            float2* p0 = reinterpret_cast<float2*>(C + (size_t)row0 * ldC + col);
            float2* p1 = reinterpret_cast<float2*>(C + (size_t)(row0 + 8) * ldC + col);
            float2 v0 = make_float2(acc[mi][ni][0], acc[mi][ni][1]);
            float2 v1 = make_float2(acc[mi][ni][2], acc[mi][ni][3]);
            if (ACC) {
                float2 o0 = *p0, o1 = *p1;
                v0.x += o0.x; v0.y += o0.y; v1.x += o1.x; v1.y += o1.y;
            }
            *p0 = v0; *p1 = v1;
        }
    }
}

// ---------------- causal depthwise conv + silu -> fp32 u and bf16 hi/lo ----------------
__global__ void k_conv(const float* __restrict__ cw, const float* __restrict__ cb) {
    int d   = threadIdx.x;               // 0..255
    int bl0 = blockIdx.x * 4;            // 4 consecutive rows, same sequence
    int l   = bl0 & (SEQ - 1);
    const float* src = g_xz + (size_t)bl0 * (2 * DI) + d;
    float w0 = cw[d * 4 + 0], w1 = cw[d * 4 + 1], w2 = cw[d * 4 + 2], w3 = cw[d * 4 + 3];
    float b  = cb[d];
    float v0, v1, v2;
    if (l == 0) { v0 = v1 = v2 = 0.f; }
    else { v0 = src[-3 * 512]; v1 = src[-2 * 512]; v2 = src[-512]; }
    float v3 = src[0], v4 = src[512], v5 = src[2 * 512], v6 = src[3 * 512];
    float va[7] = {v0, v1, v2, v3, v4, v5, v6};
#pragma unroll
    for (int j = 0; j < 4; j++) {
        float s = b;
        s = fmaf(va[j + 0], w0, s);
        s = fmaf(va[j + 1], w1, s);
        s = fmaf(va[j + 2], w2, s);
        s = fmaf(va[j + 3], w3, s);
        float sig = __fdividef(1.0f, 1.0f + __expf(-s));
        float u = s * sig;
        size_t idx = (size_t)(bl0 + j) * DI + d;
        g_xc[idx] = u;
        __nv_bfloat16 h, lo; bf16split(u, h, lo);
        g_xch[idx] = h; g_xcl[idx] = lo;
    }
}

// ---------------- delta = softplus(dt @ dt_w^T + dt_b), 4 rows/block ----------------
__global__ void k_dt(const float* __restrict__ dtw, const float* __restrict__ dtb) {
    int bl0 = blockIdx.x * 4;
    int e   = threadIdx.x;    // 0..255
    __shared__ float dts[4][DTR];
    if (e < 4 * DTR) dts[e >> 3][e & 7] = g_dbc[(size_t)(bl0 + (e >> 3)) * XPD + (e & 7)];
    __syncthreads();
    float w[DTR];
#pragma unroll
    for (int r = 0; r < DTR; r++) w[r] = dtw[e * DTR + r];
    float bb = dtb[e];
#pragma unroll
    for (int q = 0; q < 4; q++) {
        float v = bb;
#pragma unroll
        for (int r = 0; r < DTR; r++) v = fmaf(dts[q][r], w[r], v);
        float ex = __expf(-fabsf(v));
        float sp = fmaxf(v, 0.0f) + __logf(1.0f + ex);
        g_delta[(size_t)(bl0 + q) * DI + e] = sp;
    }
}

// A-structure check: A_n == (n+1)*A_0
__device__ __forceinline__ bool a_is_chain(const float* A) {
    bool f = true;
#pragma unroll
    for (int n = 0; n < DS; n++)
        f = f && (fabsf(A[n] - A[0] * (float)(n + 1)) <= 1e-3f * (float)(n + 1));
    return f;
}

// ---------------- scan pass A ----------------
__global__ void k_scanA(const float* __restrict__ Alog) {
    int d = threadIdx.x;
    int b = blockIdx.x / NCH;
    int c = blockIdx.x % NCH;
    float A[DS];
#pragma unroll
    for (int n = 0; n < DS; n++) A[n] = -__expf(Alog[d * DS + n]);
    bool fast = a_is_chain(A);
    float A0 = A[0];
    float S[DS];
#pragma unroll
    for (int n = 0; n < DS; n++) S[n] = 0.f;
    float dsum = 0.f;
    int l0 = b * SEQ + c * CH;
    const float* dp = g_delta + (size_t)l0 * DI + d;
    const float* up = g_xc    + (size_t)l0 * DI + d;
    if (fast) {
        for (int t = 0; t < CH; t++) {
            float delta = dp[t * DI];
            float du    = delta * up[t * DI];
            dsum += delta;
            const float4* bp = reinterpret_cast<const float4*>(g_dbc + (size_t)(l0 + t) * XPD + DTR);
            float4 q0 = bp[0], q1 = bp[1], q2 = bp[2], q3 = bp[3];
            float Bv[DS] = {q0.x, q0.y, q0.z, q0.w, q1.x, q1.y, q1.z, q1.w,
                            q2.x, q2.y, q2.z, q2.w, q3.x, q3.y, q3.z, q3.w};
            float w = __expf(delta * A0);
            float a = 1.f;
#pragma unroll
            for (int n = 0; n < DS; n++) {
                a *= w;
                S[n] = fmaf(a, S[n], du * Bv[n]);
            }
        }
    } else {
        for (int t = 0; t < CH; t++) {
            float delta = dp[t * DI];
            float du    = delta * up[t * DI];
            dsum += delta;
            const float4* bp = reinterpret_cast<const float4*>(g_dbc + (size_t)(l0 + t) * XPD + DTR);
            float4 q0 = bp[0], q1 = bp[1], q2 = bp[2], q3 = bp[3];
            float Bv[DS] = {q0.x, q0.y, q0.z, q0.w, q1.x, q1.y, q1.z, q1.w,
                            q2.x, q2.y, q2.z, q2.w, q3.x, q3.y, q3.z, q3.w};
#pragma unroll
            for (int n = 0; n < DS; n++) {
                float a = __expf(delta * A[n]);
                S[n] = fmaf(a, S[n], du * Bv[n]);
            }
        }
    }
    float Pv[DS];
    if (fast) {
        float pw = __expf(dsum * A0);
        float a = 1.f;
#pragma unroll
        for (int n = 0; n < DS; n++) { a *= pw; Pv[n] = a; }
    } else {
#pragma unroll
        for (int n = 0; n < DS; n++) Pv[n] = __expf(A[n] * dsum);
    }
    int o = (blockIdx.x * DI + d) * DS;
    float4* Pp = reinterpret_cast<float4*>(g_P + o);
    float4* Sp = reinterpret_cast<float4*>(g_S + o);
#pragma unroll
    for (int q = 0; q < 4; q++) {
        Pp[q] = make_float4(Pv[q*4+0], Pv[q*4+1], Pv[q*4+2], Pv[q*4+3]);
        Sp[q] = make_float4(S[q*4+0], S[q*4+1], S[q*4+2], S[q*4+3]);
    }
}

// ---------------- scan pass B ----------------
__global__ void k_scanB() {
    int idx = blockIdx.x * 256 + threadIdx.x;
    int b   = idx / (DI * DS);
    int dn  = idx - b * DI * DS;
    float h = 0.f;
    for (int c = 0; c < NCH; c++) {
        int o = (b * NCH + c) * DI * DS + dn;
        g_H0[o] = h;
        h = fmaf(g_P[o], h, g_S[o]);
    }
}

// ---------------- scan pass C: y=(h.C)+u*D, *silu(z) -> bf16 hi/lo ----------------
__global__ void k_scanC(const float* __restrict__ Alog, const float* __restrict__ Dpl) {
    int d = threadIdx.x;
    int b = blockIdx.x / NCH;
    int c = blockIdx.x % NCH;
    float A[DS];
#pragma unroll
    for (int n = 0; n < DS; n++) A[n] = -__expf(Alog[d * DS + n]);
    bool fast = a_is_chain(A);
    float A0 = A[0];
    float h[DS];
    {
        int o = (blockIdx.x * DI + d) * DS;
        const float4* Hp = reinterpret_cast<const float4*>(g_H0 + o);
#pragma unroll
        for (int q = 0; q < 4; q++) {
            float4 hv = Hp[q];
            h[q*4+0] = hv.x; h[q*4+1] = hv.y; h[q*4+2] = hv.z; h[q*4+3] = hv.w;
        }
    }
    float Dd = Dpl[d];
    int l0 = b * SEQ + c * CH;
    const float* dp = g_delta + (size_t)l0 * DI + d;
    const float* up = g_xc    + (size_t)l0 * DI + d;
    const float* zp = g_xz    + (size_t)l0 * (2 * DI) + DI + d;
    for (int t = 0; t < CH; t++) {
        float delta = dp[t * DI];
        float u     = up[t * DI];
        float du    = delta * u;
        const float4* bp = reinterpret_cast<const float4*>(g_dbc + (size_t)(l0 + t) * XPD + DTR);
        float4 q0 = bp[0], q1 = bp[1], q2 = bp[2], q3 = bp[3];
        float4 r0 = bp[4], r1 = bp[5], r2 = bp[6], r3 = bp[7];
        float Bv[DS] = {q0.x, q0.y, q0.z, q0.w, q1.x, q1.y, q1.z, q1.w,
                        q2.x, q2.y, q2.z, q2.w, q3.x, q3.y, q3.z, q3.w};
        float Cv[DS] = {r0.x, r0.y, r0.z, r0.w, r1.x, r1.y, r1.z, r1.w,
                        r2.x, r2.y, r2.z, r2.w, r3.x, r3.y, r3.z, r3.w};
        float y = 0.f;
        if (fast) {
            float w = __expf(delta * A0);
            float a = 1.f;
#pragma unroll
            for (int n = 0; n < DS; n++) {
                a *= w;
                h[n] = fmaf(a, h[n], du * Bv[n]);
                y    = fmaf(h[n], Cv[n], y);
            }
        } else {
#pragma unroll
            for (int n = 0; n < DS; n++) {
                float a = __expf(delta * A[n]);
                h[n] = fmaf(a, h[n], du * Bv[n]);
                y    = fmaf(h[n], Cv[n], y);
            }
        }
        y = fmaf(u, Dd, y);
        float z  = zp[t * (2 * DI)];
        float sz = z * __fdividef(1.0f, 1.0f + __expf(-z));
        float v = y * sz;
        size_t idx = (size_t)(l0 + t) * DI + d;
        __nv_bfloat16 hh, ll; bf16split(v, hh, ll);
        g_yh[idx] = hh; g_yl[idx] = ll;
    }
}

// ---------------- final rmsnorm + mean-pool partials ----------------
__global__ void k_pool(const float* __restrict__ nfw) {
    int b   = blockIdx.x;
    int seg = blockIdx.y;
    int m   = threadIdx.x;
    __shared__ float red[4];
    float acc = 0.f;
    float wm  = nfw[m];
    int l0 = b * SEQ + seg * 64;
    for (int r = 0; r < 64; r++) {
        float v  = g_h[(size_t)(l0 + r) * DM + m];
        float ss = v * v;
#pragma unroll
        for (int o = 16; o; o >>= 1) ss += __shfl_xor_sync(0xffffffffu, ss, o);
        if ((m & 31) == 0) red[m >> 5] = ss;
        __syncthreads();
        float tot = red[0] + red[1] + red[2] + red[3];
        acc = fmaf(v * rsqrtf(tot * (1.0f / DM) + EPS), wm, acc);
        __syncthreads();
    }
    g_poolp[(b * 32 + seg) * DM + m] = acc;
}

__global__ void k_poolred() {
    int idx = blockIdx.x * 256 + threadIdx.x;
    int b = idx / DM, m = idx % DM;
    float s = 0.f;
#pragma unroll
    for (int seg = 0; seg < 32; seg++) s += g_poolp[(b * 32 + seg) * DM + m];
    g_pooled[idx] = s;
}

__global__ void k_cls(const float* __restrict__ cw, const float* __restrict__ cb,
                      float* __restrict__ out) {
    int t = threadIdx.x;
    if (t >= NB * NCLS) return;
    int b = t / NCLS, c = t % NCLS;
    float s = 0.f;
#pragma unroll 8
    for (int m = 0; m < DM; m++) s = fmaf(g_pooled[b * DM + m], cw[c * DM + m], s);
    out[t] = s * (1.0f / SEQ) + cb[c];
}

// ---------------- launch ----------------
extern "C" void kernel_launch(void* const* d_in, const int* in_sizes, int n_in,
                              void* d_out, int out_size) {
    const float* x      = (const float*)d_in[0];
    const float* enc_w  = (const float*)d_in[1];
    const float* enc_b  = (const float*)d_in[2];
    const float* norm_w = (const float*)d_in[3];
    const float* in_w   = (const float*)d_in[4];
    const float* conv_w = (const float*)d_in[5];
    const float* conv_b = (const float*)d_in[6];
    const float* xp_w   = (const float*)d_in[7];
    const float* dt_w   = (const float*)d_in[8];
    const float* dt_b   = (const float*)d_in[9];
    const float* A_log  = (const float*)d_in[10];
    const float* Dp     = (const float*)d_in[11];
    const float* out_w  = (const float*)d_in[12];
    const float* nfw    = (const float*)d_in[13];
    const float* cls_w  = (const float*)d_in[14];
    const float* cls_b  = (const float*)d_in[15];
    float* out = (float*)d_out;

    k_cvtw<<<NLAY * 512 * 128 / 256, 256>>>(in_w, xp_w, out_w);
    k_encoder<<<BL, DM>>>(x, enc_w, enc_b);

    for (int i = 0; i < NLAY; i++) {
        k_rmsnorm<<<BL / 8, dim3(32, 8)>>>(norm_w + i * DM);
        k_mma<0><<<dim3(BL / 128, 4), 256>>>(i);
        k_conv<<<BL / 4, 256>>>(conv_w + i * DI * 4, conv_b + i * DI);
        k_mma<1><<<dim3(BL / 128, 1), 256>>>(i);
        k_dt<<<BL / 4, 256>>>(dt_w + i * DI * DTR, dt_b + i * DI);
        k_scanA<<<NB * NCH, DI>>>(A_log + i * DI * DS);
        k_scanB<<<NB * DI * DS / 256, 256>>>();
        k_scanC<<<NB * NCH, DI>>>(A_log + i * DI * DS, Dp + i * DI);
        k_mma<2><<<dim3(BL / 128, 1), 256>>>(i);
    }

    k_pool<<<dim3(NB, 32), DM>>>(nfw);
    k_poolred<<<NB * DM / 256, 256>>>();
    k_cls<<<1, 128>>>(cls_w, cls_b, out);
}

// round 10
// speedup vs baseline: 1.7235x; 1.2027x over previous
#include <cuda_runtime.h>
#include <cuda_bf16.h>
#include <math.h>
#include <cstdint>

// ---------------- problem constants ----------------
namespace {
constexpr int NB   = 16;      // batch
constexpr int SEQ  = 2048;    // L
constexpr int DM   = 128;     // d_model
constexpr int DI   = 256;     // d_inner
constexpr int DS   = 16;      // d_state
constexpr int DTR  = 8;       // dt_rank
constexpr int NLAY = 4;
constexpr int NCLS = 5;
constexpr int BL   = NB * SEQ;          // 32768 rows
constexpr int XPD  = DTR + 2 * DS;      // 40
constexpr int NCH  = 32;                // chunks per sequence
constexpr int CH   = SEQ / NCH;         // 64 steps per chunk
constexpr float EPS = 1e-5f;
}

// ---------------- scratch (static __device__, no allocs) ----------------
__device__ float g_h    [BL * DM];            // residual stream
__device__ float g_xz   [BL * 2 * DI];        // in_proj output (xm | z)
__device__ float g_xc   [BL * DI];            // conv+silu output (u), fp32 for scan
__device__ float g_dbc  [BL * XPD];           // x_proj output (dt|B|C)
__device__ float g_P    [NB * NCH * DI * DS];
__device__ float g_S    [NB * NCH * DI * DS];
__device__ float g_H0   [NB * NCH * DI * DS];
__device__ float g_poolp[NB * 32 * DM];

// bf16 hi/lo split activations (A operands)
__device__ __nv_bfloat16 g_xnh[BL * DM],  g_xnl[BL * DM];   // rmsnorm out
__device__ __nv_bfloat16 g_xch[BL * DI],  g_xcl[BL * DI];   // conv out
__device__ __nv_bfloat16 g_yh [BL * DI],  g_yl [BL * DI];   // scan out

// bf16 hi/lo split weights (B operands), xp padded 40->64 rows with zeros
__device__ __nv_bfloat16 g_wih[NLAY * 512 * 128], g_wil[NLAY * 512 * 128];
__device__ __nv_bfloat16 g_wxh[NLAY * 64 * 256],  g_wxl[NLAY * 64 * 256];
__device__ __nv_bfloat16 g_woh[NLAY * 128 * 256], g_wol[NLAY * 128 * 256];

// ---------------- helpers ----------------
__device__ __forceinline__ uint32_t smem_u32(const void* p) {
    uint32_t a;
    asm("{ .reg .u64 t; cvta.to.shared.u64 t, %1; cvt.u32.u64 %0, t; }"
        : "=r"(a) : "l"(p));
    return a;
}
__device__ __forceinline__ void ldsm4(uint32_t a, uint32_t& r0, uint32_t& r1,
                                      uint32_t& r2, uint32_t& r3) {
    asm volatile("ldmatrix.sync.aligned.m8n8.x4.shared.b16 {%0,%1,%2,%3}, [%4];"
                 : "=r"(r0), "=r"(r1), "=r"(r2), "=r"(r3) : "r"(a));
}
__device__ __forceinline__ void hmma(float* c, uint32_t a0, uint32_t a1, uint32_t a2,
                                     uint32_t a3, uint32_t b0, uint32_t b1) {
    asm volatile(
        "mma.sync.aligned.m16n8k16.row.col.f32.bf16.bf16.f32 "
        "{%0,%1,%2,%3}, {%4,%5,%6,%7}, {%8,%9}, {%0,%1,%2,%3};"
        : "+f"(c[0]), "+f"(c[1]), "+f"(c[2]), "+f"(c[3])
        : "r"(a0), "r"(a1), "r"(a2), "r"(a3), "r"(b0), "r"(b1));
}
__device__ __forceinline__ void cpa16(uint32_t dst, const void* src) {
    asm volatile("cp.async.cg.shared.global [%0], [%1], 16;" :: "r"(dst), "l"(src));
}
__device__ __forceinline__ void cpa_commit() {
    asm volatile("cp.async.commit_group;" ::: "memory");
}
template <int N> __device__ __forceinline__ void cpa_wait() {
    asm volatile("cp.async.wait_group %0;" :: "n"(N) : "memory");
}
__device__ __forceinline__ void bf16split(float x, __nv_bfloat16& h, __nv_bfloat16& l) {
    h = __float2bfloat16(x);
    l = __float2bfloat16(x - __bfloat162float(h));
}
// log-depth power ladder: a[n] = w^(n+1), n=0..15 (depth ~4 vs 16 serial)
__device__ __forceinline__ void powchain(float w, float* a) {
    float w2 = w * w;
    float w4 = w2 * w2;
    float w8 = w4 * w4;
    a[0] = w;       a[1] = w2;      a[2] = w2 * w;  a[3] = w4;
    a[4] = w4 * w;  a[5] = w4 * w2; a[6] = w4 * a[2]; a[7] = w8;
    a[8] = w8 * w;  a[9] = w8 * w2; a[10] = w8 * a[2]; a[11] = w8 * w4;
    a[12] = w8 * a[4]; a[13] = w8 * a[5]; a[14] = w8 * a[6]; a[15] = w8 * w8;
}

// ---------------- weight conversion (once per launch) ----------------
__global__ void k_cvtw(const float* __restrict__ in_w,
                       const float* __restrict__ xp_w,
                       const float* __restrict__ out_w) {
    int i = blockIdx.x * 256 + threadIdx.x;
    if (i < NLAY * 512 * 128) {
        __nv_bfloat16 h, l; bf16split(in_w[i], h, l);
        g_wih[i] = h; g_wil[i] = l;
    }
    if (i < NLAY * 64 * 256) {
        int l4 = i / (64 * 256);
        int r  = (i / 256) % 64;
        int c  = i % 256;
        float x = (r < XPD) ? xp_w[((size_t)l4 * XPD + r) * 256 + c] : 0.f;
        __nv_bfloat16 h, l; bf16split(x, h, l);
        g_wxh[i] = h; g_wxl[i] = l;
    }
    if (i < NLAY * 128 * 256) {
        __nv_bfloat16 h, l; bf16split(out_w[i], h, l);
        g_woh[i] = h; g_wol[i] = l;
    }
}

// ---------------- encoder: h = x @ enc_w^T + enc_b ----------------
__global__ void k_encoder(const float* __restrict__ x,
                          const float* __restrict__ ew,
                          const float* __restrict__ eb) {
    int row = blockIdx.x;
    int m   = threadIdx.x;
    __shared__ float xs[12];
    if (m < 12) xs[m] = x[row * 12 + m];
    __syncthreads();
    float acc = eb[m];
#pragma unroll
    for (int c = 0; c < 12; c++) acc = fmaf(xs[c], ew[m * 12 + c], acc);
    g_h[row * DM + m] = acc;
}

// ---------------- rmsnorm -> bf16 hi/lo ----------------
__global__ void k_rmsnorm(const float* __restrict__ w) {
    int row  = blockIdx.x * 8 + threadIdx.y;   // blockDim (32,8)
    int lane = threadIdx.x;
    float4 v = reinterpret_cast<const float4*>(g_h)[row * (DM / 4) + lane];
    float ss = v.x * v.x + v.y * v.y + v.z * v.z + v.w * v.w;
#pragma unroll
    for (int o = 16; o; o >>= 1) ss += __shfl_xor_sync(0xffffffffu, ss, o);
    float r = rsqrtf(ss * (1.0f / DM) + EPS);
    float4 wv = reinterpret_cast<const float4*>(w)[lane];
    float o0 = v.x * r * wv.x, o1 = v.y * r * wv.y;
    float o2 = v.z * r * wv.z, o3 = v.w * r * wv.w;
    __nv_bfloat16 h0, l0, h1, l1, h2, l2, h3, l3;
    bf16split(o0, h0, l0); bf16split(o1, h1, l1);
    bf16split(o2, h2, l2); bf16split(o3, h3, l3);
    size_t base = (size_t)row * DM + lane * 4;
    *reinterpret_cast<__nv_bfloat162*>(g_xnh + base)     = __nv_bfloat162(h0, h1);
    *reinterpret_cast<__nv_bfloat162*>(g_xnh + base + 2) = __nv_bfloat162(h2, h3);
    *reinterpret_cast<__nv_bfloat162*>(g_xnl + base)     = __nv_bfloat162(l0, l1);
    *reinterpret_cast<__nv_bfloat162*>(g_xnl + base + 2) = __nv_bfloat162(l2, l3);
}

// ---------------- HMMA 3-split GEMM, cp.async 2-stage pipelined --------------
// D = Ah*Wh + Al*Wh + Ah*Wl. Weight ptrs resolved in device code (layer idx).
// MODE 0: in_proj  A=g_xnh/l (K=128) -> g_xz  (N=512, grid.y=4)
// MODE 1: x_proj   A=g_xch/l (K=256) -> g_dbc (N=40 real, TN=64)
// MODE 2: out_proj A=g_yh/l  (K=256) -> g_h   (N=128, accumulate)
template <int MODE>
__global__ void __launch_bounds__(256, 2) k_mma(int layer) {
    constexpr int K   = (MODE == 0) ? 128 : 256;
    constexpr int TN  = (MODE == 1) ? 64 : 128;
    constexpr int NF  = TN / 16;
    constexpr bool ACC = (MODE == 2);
    constexpr int STR = 40;                       // smem row stride (bf16)
    constexpr int NC  = K / 32;                   // k-chunks
    constexpr int ASZ = 128 * STR * 2;            // bytes per A tile
    constexpr int BSZ = TN * STR * 2;             // bytes per B tile
    constexpr int STG = 2 * ASZ + 2 * BSZ;        // bytes per stage

    extern __shared__ __align__(16) char sm[];

    const __nv_bfloat16* Ah = (MODE == 0) ? g_xnh : (MODE == 1 ? g_xch : g_yh);
    const __nv_bfloat16* Al = (MODE == 0) ? g_xnl : (MODE == 1 ? g_xcl : g_yl);
    const __nv_bfloat16* Wh;
    const __nv_bfloat16* Wl;
    if (MODE == 0) {
        Wh = g_wih + (size_t)layer * 512 * 128;
        Wl = g_wil + (size_t)layer * 512 * 128;
    } else if (MODE == 1) {
        Wh = g_wxh + (size_t)layer * 64 * 256;
        Wl = g_wxl + (size_t)layer * 64 * 256;
    } else {
        Wh = g_woh + (size_t)layer * 128 * 256;
        Wl = g_wol + (size_t)layer * 128 * 256;
    }
    float* C  = (MODE == 0) ? g_xz : (MODE == 1 ? g_dbc : g_h);
    const int ldC = (MODE == 0) ? 512 : (MODE == 1 ? XPD : DM);

    const int tid = threadIdx.x;
    const int lid = tid & 31;
    const int wid = tid >> 5;
    const int mw  = wid & 3;
    const int nw  = wid >> 2;
    const int bm  = blockIdx.x * 128;
    const int bn  = blockIdx.y * TN;
    const int rb0 = mw * 32;
    const int nb0 = nw * (TN / 2);

    const uint32_t sb0 = smem_u32(sm);

    auto stage_fn = [&](int kc, int st) {
        uint32_t base = sb0 + (uint32_t)st * STG;
#pragma unroll
        for (int s = tid; s < 512; s += 256) {
            int row = s >> 2, c8 = (s & 3) * 8;
            size_t go = (size_t)(bm + row) * K + kc * 32 + c8;
            uint32_t so = (uint32_t)(row * STR + c8) * 2;
            cpa16(base + so, Ah + go);
            cpa16(base + ASZ + so, Al + go);
        }
#pragma unroll
        for (int s = tid; s < TN * 4; s += 256) {
            int row = s >> 2, c8 = (s & 3) * 8;
            size_t go = (size_t)(bn + row) * K + kc * 32 + c8;
            uint32_t so = (uint32_t)(row * STR + c8) * 2;
            cpa16(base + 2 * ASZ + so, Wh + go);
            cpa16(base + 2 * ASZ + BSZ + so, Wl + go);
        }
        cpa_commit();
    };

    // lane offsets for ldmatrix (bf16 element units)
    const int arow = (lid & 7) + ((lid >> 3) & 1) * 8;
    const int acol = (lid >> 4) * 8;
    const int brow = (lid & 7) + ((lid >> 3) >= 2 ? 8 : 0);
    const int bcol = ((lid >> 3) & 1) * 8;

    float acc[2][NF][4];
#pragma unroll
    for (int mi = 0; mi < 2; mi++)
#pragma unroll
        for (int ni = 0; ni < NF; ni++)
#pragma unroll
            for (int q = 0; q < 4; q++) acc[mi][ni][q] = 0.f;

    stage_fn(0, 0);
    if (NC > 1) stage_fn(1, 1);

    for (int kc = 0; kc < NC; kc++) {
        if (kc + 1 < NC) cpa_wait<1>(); else cpa_wait<0>();
        __syncthreads();
        uint32_t base = sb0 + (uint32_t)(kc & 1) * STG;
        uint32_t bAh = base, bAl = base + ASZ;
        uint32_t bBh = base + 2 * ASZ, bBl = base + 2 * ASZ + BSZ;
#pragma unroll
        for (int pass = 0; pass < 3; pass++) {
            uint32_t aB = (pass == 1) ? bAl : bAh;
            uint32_t bB = (pass == 2) ? bBl : bBh;
#pragma unroll
            for (int ks = 0; ks < 32; ks += 16) {
                uint32_t af[2][4];
#pragma unroll
                for (int mi = 0; mi < 2; mi++) {
                    uint32_t addr = aB +
                        (uint32_t)(((rb0 + mi * 16 + arow) * STR + ks + acol) * 2);
                    ldsm4(addr, af[mi][0], af[mi][1], af[mi][2], af[mi][3]);
                }
                uint32_t bf[NF][2];
#pragma unroll
                for (int nj = 0; nj < NF / 2; nj++) {
                    uint32_t r0, r1, r2, r3;
                    uint32_t addr = bB +
                        (uint32_t)(((nb0 + nj * 16 + brow) * STR + ks + bcol) * 2);
                    ldsm4(addr, r0, r1, r2, r3);
                    bf[nj * 2][0] = r0; bf[nj * 2][1] = r1;
                    bf[nj * 2 + 1][0] = r2; bf[nj * 2 + 1][1] = r3;
                }
#pragma unroll
                for (int mi = 0; mi < 2; mi++)
#pragma unroll
                    for (int ni = 0; ni < NF; ni++)
                        hmma(acc[mi][ni], af[mi][0], af[mi][1], af[mi][2], af[mi][3],
                             bf[ni][0], bf[ni][1]);
            }
        }
        __syncthreads();
        if (kc + 2 < NC) stage_fn(kc + 2, kc & 1);
    }

    // epilogue
    const int g = lid >> 2, t = lid & 3;
#pragma unroll
    for (int mi = 0; mi < 2; mi++) {
        int row0 = bm + rb0 + mi * 16 + g;
#pragma unroll
        for (int ni = 0; ni < NF; ni++) {
            int col = bn + nb0 + ni * 8 + t * 2;
            if (MODE == 1 && col >= XPD) continue;
            float2* p0 = reinterpret_cast<float2*>(C + (size_t)row0 * ldC + col);
            float2* p1 = reinterpret_cast<float2*>(C + (size_t)(row0 + 8) * ldC + col);
            float2 v0 = make_float2(acc[mi][ni][0], acc[mi][ni][1]);
            float2 v1 = make_float2(acc[mi][ni][2], acc[mi][ni][3]);
            if (ACC) {
                float2 o0 = *p0, o1 = *p1;
                v0.x += o0.x; v0.y += o0.y; v1.x += o1.x; v1.y += o1.y;
            }
            *p0 = v0; *p1 = v1;
        }
    }
}

// ---------------- causal depthwise conv + silu -> fp32 u and bf16 hi/lo ----------------
__global__ void k_conv(const float* __restrict__ cw, const float* __restrict__ cb) {
    int d   = threadIdx.x;               // 0..255
    int bl0 = blockIdx.x * 4;            // 4 consecutive rows, same sequence
    int l   = bl0 & (SEQ - 1);
    const float* src = g_xz + (size_t)bl0 * (2 * DI) + d;
    float w0 = cw[d * 4 + 0], w1 = cw[d * 4 + 1], w2 = cw[d * 4 + 2], w3 = cw[d * 4 + 3];
    float b  = cb[d];
    float v0, v1, v2;
    if (l == 0) { v0 = v1 = v2 = 0.f; }
    else { v0 = src[-3 * 512]; v1 = src[-2 * 512]; v2 = src[-512]; }
    float v3 = src[0], v4 = src[512], v5 = src[2 * 512], v6 = src[3 * 512];
    float va[7] = {v0, v1, v2, v3, v4, v5, v6};
#pragma unroll
    for (int j = 0; j < 4; j++) {
        float s = b;
        s = fmaf(va[j + 0], w0, s);
        s = fmaf(va[j + 1], w1, s);
        s = fmaf(va[j + 2], w2, s);
        s = fmaf(va[j + 3], w3, s);
        float sig = __fdividef(1.0f, 1.0f + __expf(-s));
        float u = s * sig;
        size_t idx = (size_t)(bl0 + j) * DI + d;
        g_xc[idx] = u;
        __nv_bfloat16 h, lo; bf16split(u, h, lo);
        g_xch[idx] = h; g_xcl[idx] = lo;
    }
}

// A-structure check: A_n == (n+1)*A_0
__device__ __forceinline__ bool a_is_chain(const float* A) {
    bool f = true;
#pragma unroll
    for (int n = 0; n < DS; n++)
        f = f && (fabsf(A[n] - A[0] * (float)(n + 1)) <= 1e-3f * (float)(n + 1));
    return f;
}
__device__ __forceinline__ float softplus_f(float v) {
    return fmaxf(v, 0.0f) + __logf(1.0f + __expf(-fabsf(v)));
}

// ---------------- scan pass A (dt fused, dbc staged in smem) ----------------
__global__ void k_scanA(const float* __restrict__ Alog,
                        const float* __restrict__ dtw,
                        const float* __restrict__ dtb) {
    __shared__ float sdbc[CH * XPD];     // 64 x 40 floats
    int d = threadIdx.x;
    int b = blockIdx.x / NCH;
    int c = blockIdx.x % NCH;
    int l0 = b * SEQ + c * CH;
    for (int s = d; s < CH * (XPD / 4); s += DI) {
        reinterpret_cast<float4*>(sdbc)[s] =
            *reinterpret_cast<const float4*>(g_dbc + (size_t)l0 * XPD + s * 4);
    }
    __syncthreads();

    float A[DS];
#pragma unroll
    for (int n = 0; n < DS; n++) A[n] = -__expf(Alog[d * DS + n]);
    bool fast = a_is_chain(A);
    float A0 = A[0];
    float wr[DTR];
#pragma unroll
    for (int r = 0; r < DTR; r++) wr[r] = dtw[d * DTR + r];
    float bb = dtb[d];

    float S[DS];
#pragma unroll
    for (int n = 0; n < DS; n++) S[n] = 0.f;
    float dsum = 0.f;
    const float* up = g_xc + (size_t)l0 * DI + d;

    for (int t = 0; t < CH; t++) {
        const float* row = sdbc + t * XPD;
        float4 d0 = *reinterpret_cast<const float4*>(row);
        float4 d1 = *reinterpret_cast<const float4*>(row + 4);
        float v = bb;
        v = fmaf(d0.x, wr[0], v); v = fmaf(d0.y, wr[1], v);
        v = fmaf(d0.z, wr[2], v); v = fmaf(d0.w, wr[3], v);
        v = fmaf(d1.x, wr[4], v); v = fmaf(d1.y, wr[5], v);
        v = fmaf(d1.z, wr[6], v); v = fmaf(d1.w, wr[7], v);
        float delta = softplus_f(v);
        float du = delta * up[t * DI];
        dsum += delta;
        float4 q0 = *reinterpret_cast<const float4*>(row + 8);
        float4 q1 = *reinterpret_cast<const float4*>(row + 12);
        float4 q2 = *reinterpret_cast<const float4*>(row + 16);
        float4 q3 = *reinterpret_cast<const float4*>(row + 20);
        float Bv[DS] = {q0.x, q0.y, q0.z, q0.w, q1.x, q1.y, q1.z, q1.w,
                        q2.x, q2.y, q2.z, q2.w, q3.x, q3.y, q3.z, q3.w};
        if (fast) {
            float a[DS];
            powchain(__expf(delta * A0), a);
#pragma unroll
            for (int n = 0; n < DS; n++) S[n] = fmaf(a[n], S[n], du * Bv[n]);
        } else {
#pragma unroll
            for (int n = 0; n < DS; n++) {
                float a = __expf(delta * A[n]);
                S[n] = fmaf(a, S[n], du * Bv[n]);
            }
        }
    }
    float Pv[DS];
    if (fast) {
        powchain(__expf(dsum * A0), Pv);
    } else {
#pragma unroll
        for (int n = 0; n < DS; n++) Pv[n] = __expf(A[n] * dsum);
    }
    int o = (blockIdx.x * DI + d) * DS;
    float4* Pp = reinterpret_cast<float4*>(g_P + o);
    float4* Sp = reinterpret_cast<float4*>(g_S + o);
#pragma unroll
    for (int q = 0; q < 4; q++) {
        Pp[q] = make_float4(Pv[q*4+0], Pv[q*4+1], Pv[q*4+2], Pv[q*4+3]);
        Sp[q] = make_float4(S[q*4+0], S[q*4+1], S[q*4+2], S[q*4+3]);
    }
}

// ---------------- scan pass B ----------------
__global__ void k_scanB() {
    int idx = blockIdx.x * 256 + threadIdx.x;
    int b   = idx / (DI * DS);
    int dn  = idx - b * DI * DS;
    float h = 0.f;
    for (int c = 0; c < NCH; c++) {
        int o = (b * NCH + c) * DI * DS + dn;
        g_H0[o] = h;
        h = fmaf(g_P[o], h, g_S[o]);
    }
}

// ---------------- scan pass C (dt fused): y=(h.C)+u*D, *silu(z) -> bf16 hi/lo ----
__global__ void k_scanC(const float* __restrict__ Alog, const float* __restrict__ Dpl,
                        const float* __restrict__ dtw, const float* __restrict__ dtb) {
    __shared__ float sdbc[CH * XPD];
    int d = threadIdx.x;
    int b = blockIdx.x / NCH;
    int c = blockIdx.x % NCH;
    int l0 = b * SEQ + c * CH;
    for (int s = d; s < CH * (XPD / 4); s += DI) {
        reinterpret_cast<float4*>(sdbc)[s] =
            *reinterpret_cast<const float4*>(g_dbc + (size_t)l0 * XPD + s * 4);
    }
    __syncthreads();

    float A[DS];
#pragma unroll
    for (int n = 0; n < DS; n++) A[n] = -__expf(Alog[d * DS + n]);
    bool fast = a_is_chain(A);
    float A0 = A[0];
    float wr[DTR];
#pragma unroll
    for (int r = 0; r < DTR; r++) wr[r] = dtw[d * DTR + r];
    float bb = dtb[d];

    float h[DS];
    {
        int o = (blockIdx.x * DI + d) * DS;
        const float4* Hp = reinterpret_cast<const float4*>(g_H0 + o);
#pragma unroll
        for (int q = 0; q < 4; q++) {
            float4 hv = Hp[q];
            h[q*4+0] = hv.x; h[q*4+1] = hv.y; h[q*4+2] = hv.z; h[q*4+3] = hv.w;
        }
    }
    float Dd = Dpl[d];
    const float* up = g_xc + (size_t)l0 * DI + d;
    const float* zp = g_xz + (size_t)l0 * (2 * DI) + DI + d;

    for (int t = 0; t < CH; t++) {
        const float* row = sdbc + t * XPD;
        float4 d0 = *reinterpret_cast<const float4*>(row);
        float4 d1 = *reinterpret_cast<const float4*>(row + 4);
        float v = bb;
        v = fmaf(d0.x, wr[0], v); v = fmaf(d0.y, wr[1], v);
        v = fmaf(d0.z, wr[2], v); v = fmaf(d0.w, wr[3], v);
        v = fmaf(d1.x, wr[4], v); v = fmaf(d1.y, wr[5], v);
        v = fmaf(d1.z, wr[6], v); v = fmaf(d1.w, wr[7], v);
        float delta = softplus_f(v);
        float u  = up[t * DI];
        float du = delta * u;
        float4 q0 = *reinterpret_cast<const float4*>(row + 8);
        float4 q1 = *reinterpret_cast<const float4*>(row + 12);
        float4 q2 = *reinterpret_cast<const float4*>(row + 16);
        float4 q3 = *reinterpret_cast<const float4*>(row + 20);
        float4 r0 = *reinterpret_cast<const float4*>(row + 24);
        float4 r1 = *reinterpret_cast<const float4*>(row + 28);
        float4 r2 = *reinterpret_cast<const float4*>(row + 32);
        float4 r3 = *reinterpret_cast<const float4*>(row + 36);
        float Bv[DS] = {q0.x, q0.y, q0.z, q0.w, q1.x, q1.y, q1.z, q1.w,
                        q2.x, q2.y, q2.z, q2.w, q3.x, q3.y, q3.z, q3.w};
        float Cv[DS] = {r0.x, r0.y, r0.z, r0.w, r1.x, r1.y, r1.z, r1.w,
                        r2.x, r2.y, r2.z, r2.w, r3.x, r3.y, r3.z, r3.w};
        float y0 = 0.f, y1 = 0.f, y2 = 0.f, y3 = 0.f;
        if (fast) {
            float a[DS];
            powchain(__expf(delta * A0), a);
#pragma unroll
            for (int n = 0; n < DS; n += 4) {
                h[n+0] = fmaf(a[n+0], h[n+0], du * Bv[n+0]);
                h[n+1] = fmaf(a[n+1], h[n+1], du * Bv[n+1]);
                h[n+2] = fmaf(a[n+2], h[n+2], du * Bv[n+2]);
                h[n+3] = fmaf(a[n+3], h[n+3], du * Bv[n+3]);
                y0 = fmaf(h[n+0], Cv[n+0], y0);
                y1 = fmaf(h[n+1], Cv[n+1], y1);
                y2 = fmaf(h[n+2], Cv[n+2], y2);
                y3 = fmaf(h[n+3], Cv[n+3], y3);
            }
        } else {
#pragma unroll
            for (int n = 0; n < DS; n++) {
                float a = __expf(delta * A[n]);
                h[n] = fmaf(a, h[n], du * Bv[n]);
                y0   = fmaf(h[n], Cv[n], y0);
            }
        }
        float y = (y0 + y1) + (y2 + y3);
        y = fmaf(u, Dd, y);
        float z  = zp[t * (2 * DI)];
        float sz = z * __fdividef(1.0f, 1.0f + __expf(-z));
        float val = y * sz;
        size_t idx = (size_t)(l0 + t) * DI + d;
        __nv_bfloat16 hh, ll; bf16split(val, hh, ll);
        g_yh[idx] = hh; g_yl[idx] = ll;
    }
}

// ---------------- final rmsnorm + mean-pool partials ----------------
__global__ void k_pool(const float* __restrict__ nfw) {
    int b   = blockIdx.x;
    int seg = blockIdx.y;
    int m   = threadIdx.x;
    __shared__ float red[4];
    float acc = 0.f;
    float wm  = nfw[m];
    int l0 = b * SEQ + seg * 64;
    for (int r = 0; r < 64; r++) {
        float v  = g_h[(size_t)(l0 + r) * DM + m];
        float ss = v * v;
#pragma unroll
        for (int o = 16; o; o >>= 1) ss += __shfl_xor_sync(0xffffffffu, ss, o);
        if ((m & 31) == 0) red[m >> 5] = ss;
        __syncthreads();
        float tot = red[0] + red[1] + red[2] + red[3];
        acc = fmaf(v * rsqrtf(tot * (1.0f / DM) + EPS), wm, acc);
        __syncthreads();
    }
    g_poolp[(b * 32 + seg) * DM + m] = acc;
}

// ---------------- pooled reduce + classifier (merged) ----------------
__global__ void k_final(const float* __restrict__ cw, const float* __restrict__ cb,
                        float* __restrict__ out) {
    __shared__ float sp[NB * DM];
    int tid = threadIdx.x;
    for (int idx = tid; idx < NB * DM; idx += 256) {
        int b = idx / DM, m = idx % DM;
        float s = 0.f;
#pragma unroll
        for (int seg = 0; seg < 32; seg++) s += g_poolp[(b * 32 + seg) * DM + m];
        sp[idx] = s;
    }
    __syncthreads();
    if (tid < NB * NCLS) {
        int b = tid / NCLS, cc = tid % NCLS;
        float s = 0.f;
#pragma unroll 8
        for (int m = 0; m < DM; m++) s = fmaf(sp[b * DM + m], cw[cc * DM + m], s);
        out[tid] = s * (1.0f / SEQ) + cb[cc];
    }
}

// ---------------- launch ----------------
namespace {
constexpr int SMEM_M0 = 2 * (2 * 128 * 40 * 2 + 2 * 128 * 40 * 2); // 81920
constexpr int SMEM_M1 = 2 * (2 * 128 * 40 * 2 + 2 * 64 * 40 * 2);  // 61440
constexpr int SMEM_M2 = SMEM_M0;
}

extern "C" void kernel_launch(void* const* d_in, const int* in_sizes, int n_in,
                              void* d_out, int out_size) {
    const float* x      = (const float*)d_in[0];
    const float* enc_w  = (const float*)d_in[1];
    const float* enc_b  = (const float*)d_in[2];
    const float* norm_w = (const float*)d_in[3];
    const float* in_w   = (const float*)d_in[4];
    const float* conv_w = (const float*)d_in[5];
    const float* conv_b = (const float*)d_in[6];
    const float* xp_w   = (const float*)d_in[7];
    const float* dt_w   = (const float*)d_in[8];
    const float* dt_b   = (const float*)d_in[9];
    const float* A_log  = (const float*)d_in[10];
    const float* Dp     = (const float*)d_in[11];
    const float* out_w  = (const float*)d_in[12];
    const float* nfw    = (const float*)d_in[13];
    const float* cls_w  = (const float*)d_in[14];
    const float* cls_b  = (const float*)d_in[15];
    float* out = (float*)d_out;

    cudaFuncSetAttribute(k_mma<0>, cudaFuncAttributeMaxDynamicSharedMemorySize, SMEM_M0);
    cudaFuncSetAttribute(k_mma<1>, cudaFuncAttributeMaxDynamicSharedMemorySize, SMEM_M1);
    cudaFuncSetAttribute(k_mma<2>, cudaFuncAttributeMaxDynamicSharedMemorySize, SMEM_M2);

    k_cvtw<<<NLAY * 512 * 128 / 256, 256>>>(in_w, xp_w, out_w);
    k_encoder<<<BL, DM>>>(x, enc_w, enc_b);

    for (int i = 0; i < NLAY; i++) {
        k_rmsnorm<<<BL / 8, dim3(32, 8)>>>(norm_w + i * DM);
        k_mma<0><<<dim3(BL / 128, 4), 256, SMEM_M0>>>(i);
        k_conv<<<BL / 4, 256>>>(conv_w + i * DI * 4, conv_b + i * DI);
        k_mma<1><<<dim3(BL / 128, 1), 256, SMEM_M1>>>(i);
        k_scanA<<<NB * NCH, DI>>>(A_log + i * DI * DS, dt_w + i * DI * DTR,
                                  dt_b + i * DI);
        k_scanB<<<NB * DI * DS / 256, 256>>>();
        k_scanC<<<NB * NCH, DI>>>(A_log + i * DI * DS, Dp + i * DI,
                                  dt_w + i * DI * DTR, dt_b + i * DI);
        k_mma<2><<<dim3(BL / 128, 1), 256, SMEM_M2>>>(i);
    }

    k_pool<<<dim3(NB, 32), DM>>>(nfw);
    k_final<<<1, 256>>>(cls_w, cls_b, out);
}

// round 11
// speedup vs baseline: 1.7340x; 1.0061x over previous
#include <cuda_runtime.h>
#include <cuda_bf16.h>
#include <math.h>
#include <cstdint>

// ---------------- problem constants ----------------
namespace {
constexpr int NB   = 16;      // batch
constexpr int SEQ  = 2048;    // L
constexpr int DM   = 128;     // d_model
constexpr int DI   = 256;     // d_inner
constexpr int DS   = 16;      // d_state
constexpr int DTR  = 8;       // dt_rank
constexpr int NLAY = 4;
constexpr int NCLS = 5;
constexpr int BL   = NB * SEQ;          // 32768 rows
constexpr int XPD  = DTR + 2 * DS;      // 40
constexpr int NCH  = 32;                // chunks per sequence
constexpr int CH   = SEQ / NCH;         // 64 steps per chunk
constexpr float EPS = 1e-5f;
}

// ---------------- scratch (static __device__, no allocs) ----------------
__device__ float g_h    [BL * DM];            // residual stream
__device__ float g_xz   [BL * 2 * DI];        // in_proj output (xm | z)
__device__ float g_xc   [BL * DI];            // conv+silu output (u), fp32 for scan
__device__ float g_dbc  [BL * XPD];           // x_proj output (dt|B|C)
__device__ float g_P    [NB * NCH * DI * DS];
__device__ float g_S    [NB * NCH * DI * DS];
__device__ float g_H0   [NB * NCH * DI * DS];
__device__ float g_poolp[NB * 32 * DM];

// bf16 hi/lo split activations (A operands)
__device__ __nv_bfloat16 g_xnh[BL * DM],  g_xnl[BL * DM];   // rmsnorm out
__device__ __nv_bfloat16 g_xch[BL * DI],  g_xcl[BL * DI];   // conv out
__device__ __nv_bfloat16 g_yh [BL * DI],  g_yl [BL * DI];   // scan out

// bf16 hi/lo split weights (B operands), xp padded 40->64 rows with zeros
__device__ __nv_bfloat16 g_wih[NLAY * 512 * 128], g_wil[NLAY * 512 * 128];
__device__ __nv_bfloat16 g_wxh[NLAY * 64 * 256],  g_wxl[NLAY * 64 * 256];
__device__ __nv_bfloat16 g_woh[NLAY * 128 * 256], g_wol[NLAY * 128 * 256];

// ---------------- helpers ----------------
__device__ __forceinline__ uint32_t smem_u32(const void* p) {
    uint32_t a;
    asm("{ .reg .u64 t; cvta.to.shared.u64 t, %1; cvt.u32.u64 %0, t; }"
        : "=r"(a) : "l"(p));
    return a;
}
__device__ __forceinline__ void ldsm4(uint32_t a, uint32_t& r0, uint32_t& r1,
                                      uint32_t& r2, uint32_t& r3) {
    asm volatile("ldmatrix.sync.aligned.m8n8.x4.shared.b16 {%0,%1,%2,%3}, [%4];"
                 : "=r"(r0), "=r"(r1), "=r"(r2), "=r"(r3) : "r"(a));
}
__device__ __forceinline__ void hmma(float* c, const uint32_t* a,
                                     uint32_t b0, uint32_t b1) {
    asm volatile(
        "mma.sync.aligned.m16n8k16.row.col.f32.bf16.bf16.f32 "
        "{%0,%1,%2,%3}, {%4,%5,%6,%7}, {%8,%9}, {%0,%1,%2,%3};"
        : "+f"(c[0]), "+f"(c[1]), "+f"(c[2]), "+f"(c[3])
        : "r"(a[0]), "r"(a[1]), "r"(a[2]), "r"(a[3]), "r"(b0), "r"(b1));
}
__device__ __forceinline__ void cpa16(uint32_t dst, const void* src) {
    asm volatile("cp.async.cg.shared.global [%0], [%1], 16;" :: "r"(dst), "l"(src));
}
__device__ __forceinline__ void cpa_commit() {
    asm volatile("cp.async.commit_group;" ::: "memory");
}
template <int N> __device__ __forceinline__ void cpa_wait() {
    asm volatile("cp.async.wait_group %0;" :: "n"(N) : "memory");
}
__device__ __forceinline__ void bf16split(float x, __nv_bfloat16& h, __nv_bfloat16& l) {
    h = __float2bfloat16(x);
    l = __float2bfloat16(x - __bfloat162float(h));
}
// log-depth power ladder: a[n] = w^(n+1), n=0..15
__device__ __forceinline__ void powchain(float w, float* a) {
    float w2 = w * w;
    float w4 = w2 * w2;
    float w8 = w4 * w4;
    a[0] = w;       a[1] = w2;      a[2] = w2 * w;  a[3] = w4;
    a[4] = w4 * w;  a[5] = w4 * w2; a[6] = w4 * a[2]; a[7] = w8;
    a[8] = w8 * w;  a[9] = w8 * w2; a[10] = w8 * a[2]; a[11] = w8 * w4;
    a[12] = w8 * a[4]; a[13] = w8 * a[5]; a[14] = w8 * a[6]; a[15] = w8 * w8;
}

// ---------------- weight conversion (once per launch) ----------------
__global__ void k_cvtw(const float* __restrict__ in_w,
                       const float* __restrict__ xp_w,
                       const float* __restrict__ out_w) {
    int i = blockIdx.x * 256 + threadIdx.x;
    if (i < NLAY * 512 * 128) {
        __nv_bfloat16 h, l; bf16split(in_w[i], h, l);
        g_wih[i] = h; g_wil[i] = l;
    }
    if (i < NLAY * 64 * 256) {
        int l4 = i / (64 * 256);
        int r  = (i / 256) % 64;
        int c  = i % 256;
        float x = (r < XPD) ? xp_w[((size_t)l4 * XPD + r) * 256 + c] : 0.f;
        __nv_bfloat16 h, l; bf16split(x, h, l);
        g_wxh[i] = h; g_wxl[i] = l;
    }
    if (i < NLAY * 128 * 256) {
        __nv_bfloat16 h, l; bf16split(out_w[i], h, l);
        g_woh[i] = h; g_wol[i] = l;
    }
}

// ---------------- encoder: h = x @ enc_w^T + enc_b, fused layer-0 rmsnorm ----
__global__ void k_encoder(const float* __restrict__ x,
                          const float* __restrict__ ew,
                          const float* __restrict__ eb,
                          const float* __restrict__ nw) {
    int row = blockIdx.x;
    int m   = threadIdx.x;          // 128 threads
    __shared__ float xs[12];
    __shared__ float red[4];
    if (m < 12) xs[m] = x[row * 12 + m];
    __syncthreads();
    float acc = eb[m];
#pragma unroll
    for (int c = 0; c < 12; c++) acc = fmaf(xs[c], ew[m * 12 + c], acc);
    g_h[row * DM + m] = acc;
    float ss = acc * acc;
#pragma unroll
    for (int o = 16; o; o >>= 1) ss += __shfl_xor_sync(0xffffffffu, ss, o);
    if ((m & 31) == 0) red[m >> 5] = ss;
    __syncthreads();
    float tot = red[0] + red[1] + red[2] + red[3];
    float r = rsqrtf(tot * (1.0f / DM) + EPS);
    float o = acc * r * nw[m];
    __nv_bfloat16 h, l; bf16split(o, h, l);
    g_xnh[(size_t)row * DM + m] = h;
    g_xnl[(size_t)row * DM + m] = l;
}

// ---------------- HMMA 3-split GEMM, cp.async pipelined, frag-sharing -------
// D = Ah*Wh + Al*Wh + Ah*Wl. Weight ptrs resolved in device code (layer idx).
// MODE 0: in_proj  A=g_xnh/l (K=128) -> g_xz  (N=512, grid.y=4)
// MODE 1: x_proj   A=g_xch/l (K=256) -> g_dbc (N=40 real, TN=64)
// MODE 2: out_proj A=g_yh/l  (K=256) -> g_h   (N=128, accumulate),
//         then fused rmsnorm of its (complete) rows -> g_xnh/l (if nwp).
template <int MODE>
__global__ void __launch_bounds__(256, 2) k_mma(int layer,
                                                const float* __restrict__ nwp) {
    constexpr int K   = (MODE == 0) ? 128 : 256;
    constexpr int TN  = (MODE == 1) ? 64 : 128;
    constexpr int NF  = TN / 16;
    constexpr bool ACC = (MODE == 2);
    constexpr int STR = 40;                       // smem row stride (bf16)
    constexpr int NC  = K / 32;                   // k-chunks
    constexpr int ASZ = 128 * STR * 2;            // bytes per A tile
    constexpr int BSZ = TN * STR * 2;             // bytes per B tile
    constexpr int STG = 2 * ASZ + 2 * BSZ;        // bytes per stage
    constexpr int CTSTR = 132;                    // fp32 epilogue tile stride

    extern __shared__ __align__(16) char sm[];

    const __nv_bfloat16* Ah = (MODE == 0) ? g_xnh : (MODE == 1 ? g_xch : g_yh);
    const __nv_bfloat16* Al = (MODE == 0) ? g_xnl : (MODE == 1 ? g_xcl : g_yl);
    const __nv_bfloat16* Wh;
    const __nv_bfloat16* Wl;
    if (MODE == 0) {
        Wh = g_wih + (size_t)layer * 512 * 128;
        Wl = g_wil + (size_t)layer * 512 * 128;
    } else if (MODE == 1) {
        Wh = g_wxh + (size_t)layer * 64 * 256;
        Wl = g_wxl + (size_t)layer * 64 * 256;
    } else {
        Wh = g_woh + (size_t)layer * 128 * 256;
        Wl = g_wol + (size_t)layer * 128 * 256;
    }
    float* C  = (MODE == 0) ? g_xz : (MODE == 1 ? g_dbc : g_h);
    const int ldC = (MODE == 0) ? 512 : (MODE == 1 ? XPD : DM);

    const int tid = threadIdx.x;
    const int lid = tid & 31;
    const int wid = tid >> 5;
    const int mw  = wid & 3;
    const int nw  = wid >> 2;
    const int bm  = blockIdx.x * 128;
    const int bn  = blockIdx.y * TN;
    const int rb0 = mw * 32;
    const int nb0 = nw * (TN / 2);

    const uint32_t sb0 = smem_u32(sm);

    auto stage_fn = [&](int kc, int st) {
        uint32_t base = sb0 + (uint32_t)st * STG;
#pragma unroll
        for (int s = tid; s < 512; s += 256) {
            int row = s >> 2, c8 = (s & 3) * 8;
            size_t go = (size_t)(bm + row) * K + kc * 32 + c8;
            uint32_t so = (uint32_t)(row * STR + c8) * 2;
            cpa16(base + so, Ah + go);
            cpa16(base + ASZ + so, Al + go);
        }
#pragma unroll
        for (int s = tid; s < TN * 4; s += 256) {
            int row = s >> 2, c8 = (s & 3) * 8;
            size_t go = (size_t)(bn + row) * K + kc * 32 + c8;
            uint32_t so = (uint32_t)(row * STR + c8) * 2;
            cpa16(base + 2 * ASZ + so, Wh + go);
            cpa16(base + 2 * ASZ + BSZ + so, Wl + go);
        }
        cpa_commit();
    };

    // lane offsets for ldmatrix (bf16 element units)
    const int arow = (lid & 7) + ((lid >> 3) & 1) * 8;
    const int acol = (lid >> 4) * 8;
    const int brow = (lid & 7) + ((lid >> 3) >= 2 ? 8 : 0);
    const int bcol = ((lid >> 3) & 1) * 8;

    float acc[2][NF][4];
#pragma unroll
    for (int mi = 0; mi < 2; mi++)
#pragma unroll
        for (int ni = 0; ni < NF; ni++)
#pragma unroll
            for (int q = 0; q < 4; q++) acc[mi][ni][q] = 0.f;

    stage_fn(0, 0);
    if (NC > 1) stage_fn(1, 1);

    for (int kc = 0; kc < NC; kc++) {
        if (kc + 1 < NC) cpa_wait<1>(); else cpa_wait<0>();
        __syncthreads();
        uint32_t base = sb0 + (uint32_t)(kc & 1) * STG;
        uint32_t bAh = base, bAl = base + ASZ;
        uint32_t bBh = base + 2 * ASZ, bBl = base + 2 * ASZ + BSZ;
#pragma unroll
        for (int ks = 0; ks < 32; ks += 16) {
            // load A fragments once (shared by passes 0 and 2)
            uint32_t ah[2][4], al[2][4];
#pragma unroll
            for (int mi = 0; mi < 2; mi++) {
                uint32_t aoff =
                    (uint32_t)(((rb0 + mi * 16 + arow) * STR + ks + acol) * 2);
                ldsm4(bAh + aoff, ah[mi][0], ah[mi][1], ah[mi][2], ah[mi][3]);
                ldsm4(bAl + aoff, al[mi][0], al[mi][1], al[mi][2], al[mi][3]);
            }
            // process N fragments in groups of 4 (keeps live regs bounded)
#pragma unroll
            for (int ng = 0; ng < NF; ng += 4) {
                uint32_t bh[4][2], bl[4][2];
#pragma unroll
                for (int lj = 0; lj < 2; lj++) {
                    int rowb = nb0 + (ng / 2 + lj) * 16;
                    uint32_t boff =
                        (uint32_t)(((rowb + brow) * STR + ks + bcol) * 2);
                    uint32_t r0, r1, r2, r3;
                    ldsm4(bBh + boff, r0, r1, r2, r3);
                    bh[lj * 2][0] = r0; bh[lj * 2][1] = r1;
                    bh[lj * 2 + 1][0] = r2; bh[lj * 2 + 1][1] = r3;
                    ldsm4(bBl + boff, r0, r1, r2, r3);
                    bl[lj * 2][0] = r0; bl[lj * 2][1] = r1;
                    bl[lj * 2 + 1][0] = r2; bl[lj * 2 + 1][1] = r3;
                }
#pragma unroll
                for (int mi = 0; mi < 2; mi++)
#pragma unroll
                    for (int nf = 0; nf < 4; nf++) {
                        float* a = acc[mi][ng + nf];
                        hmma(a, ah[mi], bh[nf][0], bh[nf][1]);
                        hmma(a, al[mi], bh[nf][0], bh[nf][1]);
                        hmma(a, ah[mi], bl[nf][0], bl[nf][1]);
                    }
            }
        }
        __syncthreads();
        if (kc + 2 < NC) stage_fn(kc + 2, kc & 1);
    }

    // epilogue
    float* ct = reinterpret_cast<float*>(sm);   // fp32 tile for MODE 2 fusion
    const int g = lid >> 2, t = lid & 3;
#pragma unroll
    for (int mi = 0; mi < 2; mi++) {
        int row0 = bm + rb0 + mi * 16 + g;
#pragma unroll
        for (int ni = 0; ni < NF; ni++) {
            int col = bn + nb0 + ni * 8 + t * 2;
            if (MODE == 1 && col >= XPD) continue;
            float2* p0 = reinterpret_cast<float2*>(C + (size_t)row0 * ldC + col);
            float2* p1 = reinterpret_cast<float2*>(C + (size_t)(row0 + 8) * ldC + col);
            float2 v0 = make_float2(acc[mi][ni][0], acc[mi][ni][1]);
            float2 v1 = make_float2(acc[mi][ni][2], acc[mi][ni][3]);
            if (ACC) {
                float2 o0 = *p0, o1 = *p1;
                v0.x += o0.x; v0.y += o0.y; v1.x += o1.x; v1.y += o1.y;
            }
            *p0 = v0; *p1 = v1;
            if (MODE == 2) {
                int lr0 = rb0 + mi * 16 + g;
                ct[lr0 * CTSTR + col] = v0.x; ct[lr0 * CTSTR + col + 1] = v0.y;
                ct[(lr0 + 8) * CTSTR + col] = v1.x; ct[(lr0 + 8) * CTSTR + col + 1] = v1.y;
            }
        }
    }
    // MODE 2: fused rmsnorm of this block's 128 complete rows -> next layer input
    if (MODE == 2 && nwp != nullptr) {
        __syncthreads();
        float4 wv = reinterpret_cast<const float4*>(nwp)[lid];
#pragma unroll 4
        for (int rr = 0; rr < 16; rr++) {
            int lr = wid * 16 + rr;
            float4 v = *reinterpret_cast<const float4*>(ct + lr * CTSTR + lid * 4);
            float ss = v.x * v.x + v.y * v.y + v.z * v.z + v.w * v.w;
#pragma unroll
            for (int o = 16; o; o >>= 1) ss += __shfl_xor_sync(0xffffffffu, ss, o);
            float rn = rsqrtf(ss * (1.0f / DM) + EPS);
            float o0 = v.x * rn * wv.x, o1 = v.y * rn * wv.y;
            float o2 = v.z * rn * wv.z, o3 = v.w * rn * wv.w;
            __nv_bfloat16 h0, l0, h1, l1, h2, l2, h3, l3;
            bf16split(o0, h0, l0); bf16split(o1, h1, l1);
            bf16split(o2, h2, l2); bf16split(o3, h3, l3);
            size_t base = (size_t)(bm + lr) * DM + lid * 4;
            *reinterpret_cast<__nv_bfloat162*>(g_xnh + base)     = __nv_bfloat162(h0, h1);
            *reinterpret_cast<__nv_bfloat162*>(g_xnh + base + 2) = __nv_bfloat162(h2, h3);
            *reinterpret_cast<__nv_bfloat162*>(g_xnl + base)     = __nv_bfloat162(l0, l1);
            *reinterpret_cast<__nv_bfloat162*>(g_xnl + base + 2) = __nv_bfloat162(l2, l3);
        }
    }
}

// ---------------- causal depthwise conv + silu -> fp32 u and bf16 hi/lo ----------------
__global__ void k_conv(const float* __restrict__ cw, const float* __restrict__ cb) {
    int d   = threadIdx.x;               // 0..255
    int bl0 = blockIdx.x * 4;            // 4 consecutive rows, same sequence
    int l   = bl0 & (SEQ - 1);
    const float* src = g_xz + (size_t)bl0 * (2 * DI) + d;
    float w0 = cw[d * 4 + 0], w1 = cw[d * 4 + 1], w2 = cw[d * 4 + 2], w3 = cw[d * 4 + 3];
    float b  = cb[d];
    float v0, v1, v2;
    if (l == 0) { v0 = v1 = v2 = 0.f; }
    else { v0 = src[-3 * 512]; v1 = src[-2 * 512]; v2 = src[-512]; }
    float v3 = src[0], v4 = src[512], v5 = src[2 * 512], v6 = src[3 * 512];
    float va[7] = {v0, v1, v2, v3, v4, v5, v6};
#pragma unroll
    for (int j = 0; j < 4; j++) {
        float s = b;
        s = fmaf(va[j + 0], w0, s);
        s = fmaf(va[j + 1], w1, s);
        s = fmaf(va[j + 2], w2, s);
        s = fmaf(va[j + 3], w3, s);
        float sig = __fdividef(1.0f, 1.0f + __expf(-s));
        float u = s * sig;
        size_t idx = (size_t)(bl0 + j) * DI + d;
        g_xc[idx] = u;
        __nv_bfloat16 h, lo; bf16split(u, h, lo);
        g_xch[idx] = h; g_xcl[idx] = lo;
    }
}

// A-structure check: A_n == (n+1)*A_0
__device__ __forceinline__ bool a_is_chain(const float* A) {
    bool f = true;
#pragma unroll
    for (int n = 0; n < DS; n++)
        f = f && (fabsf(A[n] - A[0] * (float)(n + 1)) <= 1e-3f * (float)(n + 1));
    return f;
}
__device__ __forceinline__ float softplus_f(float v) {
    return fmaxf(v, 0.0f) + __logf(1.0f + __expf(-fabsf(v)));
}

// ---------------- scan pass A (dt fused, dbc staged in smem) ----------------
__global__ void k_scanA(const float* __restrict__ Alog,
                        const float* __restrict__ dtw,
                        const float* __restrict__ dtb) {
    __shared__ float sdbc[CH * XPD];     // 64 x 40 floats
    int d = threadIdx.x;
    int b = blockIdx.x / NCH;
    int c = blockIdx.x % NCH;
    int l0 = b * SEQ + c * CH;
    for (int s = d; s < CH * (XPD / 4); s += DI) {
        reinterpret_cast<float4*>(sdbc)[s] =
            *reinterpret_cast<const float4*>(g_dbc + (size_t)l0 * XPD + s * 4);
    }
    __syncthreads();

    float A[DS];
#pragma unroll
    for (int n = 0; n < DS; n++) A[n] = -__expf(Alog[d * DS + n]);
    bool fast = a_is_chain(A);
    float A0 = A[0];
    float wr[DTR];
#pragma unroll
    for (int r = 0; r < DTR; r++) wr[r] = dtw[d * DTR + r];
    float bb = dtb[d];

    float S[DS];
#pragma unroll
    for (int n = 0; n < DS; n++) S[n] = 0.f;
    float dsum = 0.f;
    const float* up = g_xc + (size_t)l0 * DI + d;

    for (int t = 0; t < CH; t++) {
        const float* row = sdbc + t * XPD;
        float4 d0 = *reinterpret_cast<const float4*>(row);
        float4 d1 = *reinterpret_cast<const float4*>(row + 4);
        float v = bb;
        v = fmaf(d0.x, wr[0], v); v = fmaf(d0.y, wr[1], v);
        v = fmaf(d0.z, wr[2], v); v = fmaf(d0.w, wr[3], v);
        v = fmaf(d1.x, wr[4], v); v = fmaf(d1.y, wr[5], v);
        v = fmaf(d1.z, wr[6], v); v = fmaf(d1.w, wr[7], v);
        float delta = softplus_f(v);
        float du = delta * up[t * DI];
        dsum += delta;
        float4 q0 = *reinterpret_cast<const float4*>(row + 8);
        float4 q1 = *reinterpret_cast<const float4*>(row + 12);
        float4 q2 = *reinterpret_cast<const float4*>(row + 16);
        float4 q3 = *reinterpret_cast<const float4*>(row + 20);
        float Bv[DS] = {q0.x, q0.y, q0.z, q0.w, q1.x, q1.y, q1.z, q1.w,
                        q2.x, q2.y, q2.z, q2.w, q3.x, q3.y, q3.z, q3.w};
        if (fast) {
            float a[DS];
            powchain(__expf(delta * A0), a);
#pragma unroll
            for (int n = 0; n < DS; n++) S[n] = fmaf(a[n], S[n], du * Bv[n]);
        } else {
#pragma unroll
            for (int n = 0; n < DS; n++) {
                float a = __expf(delta * A[n]);
                S[n] = fmaf(a, S[n], du * Bv[n]);
            }
        }
    }
    float Pv[DS];
    if (fast) {
        powchain(__expf(dsum * A0), Pv);
    } else {
#pragma unroll
        for (int n = 0; n < DS; n++) Pv[n] = __expf(A[n] * dsum);
    }
    int o = (blockIdx.x * DI + d) * DS;
    float4* Pp = reinterpret_cast<float4*>(g_P + o);
    float4* Sp = reinterpret_cast<float4*>(g_S + o);
#pragma unroll
    for (int q = 0; q < 4; q++) {
        Pp[q] = make_float4(Pv[q*4+0], Pv[q*4+1], Pv[q*4+2], Pv[q*4+3]);
        Sp[q] = make_float4(S[q*4+0], S[q*4+1], S[q*4+2], S[q*4+3]);
    }
}

// ---------------- scan pass B ----------------
__global__ void k_scanB() {
    int idx = blockIdx.x * 256 + threadIdx.x;
    int b   = idx / (DI * DS);
    int dn  = idx - b * DI * DS;
    float h = 0.f;
    for (int c = 0; c < NCH; c++) {
        int o = (b * NCH + c) * DI * DS + dn;
        g_H0[o] = h;
        h = fmaf(g_P[o], h, g_S[o]);
    }
}

// ---------------- scan pass C (dt fused): y=(h.C)+u*D, *silu(z) -> bf16 hi/lo ----
__global__ void k_scanC(const float* __restrict__ Alog, const float* __restrict__ Dpl,
                        const float* __restrict__ dtw, const float* __restrict__ dtb) {
    __shared__ float sdbc[CH * XPD];
    int d = threadIdx.x;
    int b = blockIdx.x / NCH;
    int c = blockIdx.x % NCH;
    int l0 = b * SEQ + c * CH;
    for (int s = d; s < CH * (XPD / 4); s += DI) {
        reinterpret_cast<float4*>(sdbc)[s] =
            *reinterpret_cast<const float4*>(g_dbc + (size_t)l0 * XPD + s * 4);
    }
    __syncthreads();

    float A[DS];
#pragma unroll
    for (int n = 0; n < DS; n++) A[n] = -__expf(Alog[d * DS + n]);
    bool fast = a_is_chain(A);
    float A0 = A[0];
    float wr[DTR];
#pragma unroll
    for (int r = 0; r < DTR; r++) wr[r] = dtw[d * DTR + r];
    float bb = dtb[d];

    float h[DS];
    {
        int o = (blockIdx.x * DI + d) * DS;
        const float4* Hp = reinterpret_cast<const float4*>(g_H0 + o);
#pragma unroll
        for (int q = 0; q < 4; q++) {
            float4 hv = Hp[q];
            h[q*4+0] = hv.x; h[q*4+1] = hv.y; h[q*4+2] = hv.z; h[q*4+3] = hv.w;
        }
    }
    float Dd = Dpl[d];
    const float* up = g_xc + (size_t)l0 * DI + d;
    const float* zp = g_xz + (size_t)l0 * (2 * DI) + DI + d;

    for (int t = 0; t < CH; t++) {
        const float* row = sdbc + t * XPD;
        float4 d0 = *reinterpret_cast<const float4*>(row);
        float4 d1 = *reinterpret_cast<const float4*>(row + 4);
        float v = bb;
        v = fmaf(d0.x, wr[0], v); v = fmaf(d0.y, wr[1], v);
        v = fmaf(d0.z, wr[2], v); v = fmaf(d0.w, wr[3], v);
        v = fmaf(d1.x, wr[4], v); v = fmaf(d1.y, wr[5], v);
        v = fmaf(d1.z, wr[6], v); v = fmaf(d1.w, wr[7], v);
        float delta = softplus_f(v);
        float u  = up[t * DI];
        float du = delta * u;
        float4 q0 = *reinterpret_cast<const float4*>(row + 8);
        float4 q1 = *reinterpret_cast<const float4*>(row + 12);
        float4 q2 = *reinterpret_cast<const float4*>(row + 16);
        float4 q3 = *reinterpret_cast<const float4*>(row + 20);
        float4 r0 = *reinterpret_cast<const float4*>(row + 24);
        float4 r1 = *reinterpret_cast<const float4*>(row + 28);
        float4 r2 = *reinterpret_cast<const float4*>(row + 32);
        float4 r3 = *reinterpret_cast<const float4*>(row + 36);
        float Bv[DS] = {q0.x, q0.y, q0.z, q0.w, q1.x, q1.y, q1.z, q1.w,
                        q2.x, q2.y, q2.z, q2.w, q3.x, q3.y, q3.z, q3.w};
        float Cv[DS] = {r0.x, r0.y, r0.z, r0.w, r1.x, r1.y, r1.z, r1.w,
                        r2.x, r2.y, r2.z, r2.w, r3.x, r3.y, r3.z, r3.w};
        float y0 = 0.f, y1 = 0.f, y2 = 0.f, y3 = 0.f;
        if (fast) {
            float a[DS];
            powchain(__expf(delta * A0), a);
#pragma unroll
            for (int n = 0; n < DS; n += 4) {
                h[n+0] = fmaf(a[n+0], h[n+0], du * Bv[n+0]);
                h[n+1] = fmaf(a[n+1], h[n+1], du * Bv[n+1]);
                h[n+2] = fmaf(a[n+2], h[n+2], du * Bv[n+2]);
                h[n+3] = fmaf(a[n+3], h[n+3], du * Bv[n+3]);
                y0 = fmaf(h[n+0], Cv[n+0], y0);
                y1 = fmaf(h[n+1], Cv[n+1], y1);
                y2 = fmaf(h[n+2], Cv[n+2], y2);
                y3 = fmaf(h[n+3], Cv[n+3], y3);
            }
        } else {
#pragma unroll
            for (int n = 0; n < DS; n++) {
                float a = __expf(delta * A[n]);
                h[n] = fmaf(a, h[n], du * Bv[n]);
                y0   = fmaf(h[n], Cv[n], y0);
            }
        }
        float y = (y0 + y1) + (y2 + y3);
        y = fmaf(u, Dd, y);
        float z  = zp[t * (2 * DI)];
        float sz = z * __fdividef(1.0f, 1.0f + __expf(-z));
        float val = y * sz;
        size_t idx = (size_t)(l0 + t) * DI + d;
        __nv_bfloat16 hh, ll; bf16split(val, hh, ll);
        g_yh[idx] = hh; g_yl[idx] = ll;
    }
}

// ---------------- final rmsnorm + mean-pool partials ----------------
__global__ void k_pool(const float* __restrict__ nfw) {
    int b   = blockIdx.x;
    int seg = blockIdx.y;
    int m   = threadIdx.x;
    __shared__ float red[4];
    float acc = 0.f;
    float wm  = nfw[m];
    int l0 = b * SEQ + seg * 64;
    for (int r = 0; r < 64; r++) {
        float v  = g_h[(size_t)(l0 + r) * DM + m];
        float ss = v * v;
#pragma unroll
        for (int o = 16; o; o >>= 1) ss += __shfl_xor_sync(0xffffffffu, ss, o);
        if ((m & 31) == 0) red[m >> 5] = ss;
        __syncthreads();
        float tot = red[0] + red[1] + red[2] + red[3];
        acc = fmaf(v * rsqrtf(tot * (1.0f / DM) + EPS), wm, acc);
        __syncthreads();
    }
    g_poolp[(b * 32 + seg) * DM + m] = acc;
}

// ---------------- pooled reduce + classifier (merged) ----------------
__global__ void k_final(const float* __restrict__ cw, const float* __restrict__ cb,
                        float* __restrict__ out) {
    __shared__ float sp[NB * DM];
    int tid = threadIdx.x;
    for (int idx = tid; idx < NB * DM; idx += 256) {
        int b = idx / DM, m = idx % DM;
        float s = 0.f;
#pragma unroll
        for (int seg = 0; seg < 32; seg++) s += g_poolp[(b * 32 + seg) * DM + m];
        sp[idx] = s;
    }
    __syncthreads();
    if (tid < NB * NCLS) {
        int b = tid / NCLS, cc = tid % NCLS;
        float s = 0.f;
#pragma unroll 8
        for (int m = 0; m < DM; m++) s = fmaf(sp[b * DM + m], cw[cc * DM + m], s);
        out[tid] = s * (1.0f / SEQ) + cb[cc];
    }
}

// ---------------- launch ----------------
namespace {
constexpr int SMEM_M0 = 2 * (2 * 128 * 40 * 2 + 2 * 128 * 40 * 2); // 81920
constexpr int SMEM_M1 = 2 * (2 * 128 * 40 * 2 + 2 * 64 * 40 * 2);  // 61440
constexpr int SMEM_M2 = SMEM_M0;  // also covers 128*132*4 = 67584 fp32 tile
}

extern "C" void kernel_launch(void* const* d_in, const int* in_sizes, int n_in,
                              void* d_out, int out_size) {
    const float* x      = (const float*)d_in[0];
    const float* enc_w  = (const float*)d_in[1];
    const float* enc_b  = (const float*)d_in[2];
    const float* norm_w = (const float*)d_in[3];
    const float* in_w   = (const float*)d_in[4];
    const float* conv_w = (const float*)d_in[5];
    const float* conv_b = (const float*)d_in[6];
    const float* xp_w   = (const float*)d_in[7];
    const float* dt_w   = (const float*)d_in[8];
    const float* dt_b   = (const float*)d_in[9];
    const float* A_log  = (const float*)d_in[10];
    const float* Dp     = (const float*)d_in[11];
    const float* out_w  = (const float*)d_in[12];
    const float* nfw    = (const float*)d_in[13];
    const float* cls_w  = (const float*)d_in[14];
    const float* cls_b  = (const float*)d_in[15];
    float* out = (float*)d_out;

    cudaFuncSetAttribute(k_mma<0>, cudaFuncAttributeMaxDynamicSharedMemorySize, SMEM_M0);
    cudaFuncSetAttribute(k_mma<1>, cudaFuncAttributeMaxDynamicSharedMemorySize, SMEM_M1);
    cudaFuncSetAttribute(k_mma<2>, cudaFuncAttributeMaxDynamicSharedMemorySize, SMEM_M2);

    k_cvtw<<<NLAY * 512 * 128 / 256, 256>>>(in_w, xp_w, out_w);
    k_encoder<<<BL, DM>>>(x, enc_w, enc_b, norm_w);   // fused layer-0 rmsnorm

    for (int i = 0; i < NLAY; i++) {
        k_mma<0><<<dim3(BL / 128, 4), 256, SMEM_M0>>>(i, nullptr);
        k_conv<<<BL / 4, 256>>>(conv_w + i * DI * 4, conv_b + i * DI);
        k_mma<1><<<dim3(BL / 128, 1), 256, SMEM_M1>>>(i, nullptr);
        k_scanA<<<NB * NCH, DI>>>(A_log + i * DI * DS, dt_w + i * DI * DTR,
                                  dt_b + i * DI);
        k_scanB<<<NB * DI * DS / 256, 256>>>();
        k_scanC<<<NB * NCH, DI>>>(A_log + i * DI * DS, Dp + i * DI,
                                  dt_w + i * DI * DTR, dt_b + i * DI);
        // fused: residual add + next layer's rmsnorm (except last layer)
        k_mma<2><<<dim3(BL / 128, 1), 256, SMEM_M2>>>(
            i, (i < NLAY - 1) ? (norm_w + (i + 1) * DM) : nullptr);
    }

    k_pool<<<dim3(NB, 32), DM>>>(nfw);
    k_final<<<1, 256>>>(cls_w, cls_b, out);
}